// round 8
// baseline (speedup 1.0000x reference)
#include <cuda_runtime.h>
#include <cuda_bf16.h>
#include <mma.h>
#include <cstdint>
#include <math.h>

using namespace nvcuda;

#define B_    4
#define DE    128
#define DO    512
#define THW   10240
#define HW    1024
#define NCHUNK 80
#define SCALE 0.08838834764831845f
#define INV2SIG2 (1.0f/18.0f)

// ---------------- device scratch ----------------
__device__ float         g_p[(size_t)B_ * THW * HW];       // p fp32 (preserved)
__device__ __nv_bfloat16 g_ehi[(size_t)B_ * HW * THW];     // e^T [b][q][t] hi
__device__ __nv_bfloat16 g_elo[(size_t)B_ * HW * THW];
__device__ __nv_bfloat16 g_mohi[(size_t)B_ * DO * THW];
__device__ __nv_bfloat16 g_molo[(size_t)B_ * DO * THW];
__device__ __nv_bfloat16 g_mi0[(size_t)B_ * DE * THW];     // mi 3 limbs [b][d][t]
__device__ __nv_bfloat16 g_mi1[(size_t)B_ * DE * THW];
__device__ __nv_bfloat16 g_mi2[(size_t)B_ * DE * THW];
__device__ __nv_bfloat16 g_qi0[(size_t)B_ * DE * HW];      // qi*SCALE 3 limbs [b][d][q]
__device__ __nv_bfloat16 g_qi1[(size_t)B_ * DE * HW];
__device__ __nv_bfloat16 g_qi2[(size_t)B_ * DE * HW];
__device__ float         g_c[(size_t)B_ * DO * HW];        // raw GEMM2 result
__device__ float2        g_center[B_ * THW];
__device__ float2        g_amax[(size_t)B_ * THW * 8];     // per-qtile argmax partials
__device__ float         g_part[(size_t)B_ * NCHUNK * HW];
__device__ float         g_inv[B_ * HW];

__device__ __forceinline__ void cp16(uint32_t sa, const void* g) {
    asm volatile("cp.async.cg.shared.global [%0], [%1], 16;" :: "r"(sa), "l"(g));
}
#define CP_COMMIT() asm volatile("cp.async.commit_group;" ::: "memory")
#define CP_WAIT(n)  asm volatile("cp.async.wait_group %0;" :: "n"(n) : "memory")

// ============================================================
// split fp32 -> 3 bf16 limbs (optional scale), float4 granularity
// ============================================================
__global__ void __launch_bounds__(256) split3_kernel(
    const float* __restrict__ in, __nv_bfloat16* __restrict__ o0,
    __nv_bfloat16* __restrict__ o1, __nv_bfloat16* __restrict__ o2,
    size_t n4, float scale)
{
    const size_t stride = (size_t)gridDim.x * 256;
    for (size_t i = (size_t)blockIdx.x * 256 + threadIdx.x; i < n4; i += stride) {
        float4 v = ((const float4*)in)[i];
        v.x *= scale; v.y *= scale; v.z *= scale; v.w *= scale;
        float f[4] = {v.x, v.y, v.z, v.w};
        uint16_t l0[4], l1[4], l2[4];
        #pragma unroll
        for (int k = 0; k < 4; k++) {
            __nv_bfloat16 h0 = __float2bfloat16(f[k]);
            float r = f[k] - __bfloat162float(h0);
            __nv_bfloat16 h1 = __float2bfloat16(r);
            float r2 = r - __bfloat162float(h1);
            __nv_bfloat16 h2 = __float2bfloat16(r2);
            l0[k] = *(uint16_t*)&h0; l1[k] = *(uint16_t*)&h1; l2[k] = *(uint16_t*)&h2;
        }
        ((uint2*)o0)[i] = make_uint2(l0[0] | ((uint32_t)l0[1] << 16), l0[2] | ((uint32_t)l0[3] << 16));
        ((uint2*)o1)[i] = make_uint2(l1[0] | ((uint32_t)l1[1] << 16), l1[2] | ((uint32_t)l1[3] << 16));
        ((uint2*)o2)[i] = make_uint2(l2[0] | ((uint32_t)l2[1] << 16), l2[2] | ((uint32_t)l2[3] << 16));
    }
}

// mo fp32 -> bf16 hi/lo (2 limbs, for GEMM2)
__global__ void __launch_bounds__(256) split_kernel(const float* __restrict__ in)
{
    const size_t n4 = (size_t)B_ * DO * THW / 4;
    const size_t stride = (size_t)gridDim.x * 256;
    for (size_t i = (size_t)blockIdx.x * 256 + threadIdx.x; i < n4; i += stride) {
        float4 v = ((const float4*)in)[i];
        __nv_bfloat16 h0 = __float2bfloat16(v.x), h1 = __float2bfloat16(v.y);
        __nv_bfloat16 h2 = __float2bfloat16(v.z), h3 = __float2bfloat16(v.w);
        __nv_bfloat162* H = (__nv_bfloat162*)g_mohi;
        __nv_bfloat162* L = (__nv_bfloat162*)g_molo;
        H[2*i]   = __halves2bfloat162(h0, h1);
        H[2*i+1] = __halves2bfloat162(h2, h3);
        L[2*i]   = __halves2bfloat162(__float2bfloat16(v.x - __bfloat162float(h0)),
                                      __float2bfloat16(v.y - __bfloat162float(h1)));
        L[2*i+1] = __halves2bfloat162(__float2bfloat16(v.z - __bfloat162float(h2)),
                                      __float2bfloat16(v.w - __bfloat162float(h3)));
    }
}

// ============================================================
// WMMA bf16 GEMM1 (3-limb, 6 passes): p = (mi)^T (qi*SCALE)
// 512 threads / 16 warps (4x4), warp tile 32(t) x 32(q)
// tile 128t x 128q, K = DE = 128, chunk 32, 2-stage cp.async
// epilogue: smem roundtrip -> coalesced p store + fused argmax partials
// ============================================================
#define TP 136
#define G1_TILE (32 * TP)                       // bf16 elems per limb tile
#define G1_STAGE (6 * G1_TILE)
#define G1_SMEM (2 * G1_STAGE * 2)              // 104448 bytes

__global__ void __launch_bounds__(512) gemm1_wmma(float* __restrict__ p)
{
    extern __shared__ __nv_bfloat16 dsm[];
    const int b = blockIdx.z;
    const int q0 = blockIdx.x * 128, t0 = blockIdx.y * 128;
    const int tid = threadIdx.x, wid = tid >> 5;
    const int wm = wid & 3, wn = wid >> 2;       // 4x4 warps, tile 32(t) x 32(q)

    const __nv_bfloat16* A0 = g_mi0 + (size_t)b * DE * THW;
    const __nv_bfloat16* A1 = g_mi1 + (size_t)b * DE * THW;
    const __nv_bfloat16* A2 = g_mi2 + (size_t)b * DE * THW;
    const __nv_bfloat16* B0 = g_qi0 + (size_t)b * DE * HW;
    const __nv_bfloat16* B1 = g_qi1 + (size_t)b * DE * HW;
    const __nv_bfloat16* B2 = g_qi2 + (size_t)b * DE * HW;

    const uint32_t sbase = (uint32_t)__cvta_generic_to_shared(dsm);

    auto load_stage = [&](int slot, int k0) {
        uint32_t sb = sbase + (uint32_t)slot * (G1_STAGE * 2);
        #pragma unroll
        for (int l = 0; l < 6; l++) {
            int idx = tid + l * 512;             // 0..3071
            int arr = idx >> 9, rem = idx & 511;
            int row = rem >> 4, col = rem & 15;  // row<32 (d), col*8 elems
            const __nv_bfloat16* src;
            if (arr < 3) {
                src = (arr == 0 ? A0 : arr == 1 ? A1 : A2)
                      + (size_t)(k0 + row) * THW + t0 + col * 8;
            } else {
                src = (arr == 3 ? B0 : arr == 4 ? B1 : B2)
                      + (size_t)(k0 + row) * HW + q0 + col * 8;
            }
            cp16(sb + (uint32_t)arr * (G1_TILE * 2) + row * (TP * 2) + col * 16, src);
        }
    };

    wmma::fragment<wmma::accumulator, 16, 16, 16, float> fc[2][2];
    #pragma unroll
    for (int i = 0; i < 2; i++)
        #pragma unroll
        for (int j = 0; j < 2; j++) wmma::fill_fragment(fc[i][j], 0.f);

    const int NC = DE / 32;   // 4
    load_stage(0, 0);
    CP_COMMIT();

    for (int c = 0; c < NC; c++) {
        if (c + 1 < NC) { load_stage((c + 1) & 1, (c + 1) * 32); CP_COMMIT(); }
        if (c + 1 < NC) CP_WAIT(1); else CP_WAIT(0);
        __syncthreads();

        __nv_bfloat16* st = dsm + (size_t)(c & 1) * G1_STAGE;
        #pragma unroll
        for (int kk = 0; kk < 32; kk += 16) {
            wmma::fragment<wmma::matrix_a, 16, 16, 16, __nv_bfloat16, wmma::col_major> fa[3][2];
            wmma::fragment<wmma::matrix_b, 16, 16, 16, __nv_bfloat16, wmma::row_major> fb[3][2];
            #pragma unroll
            for (int l = 0; l < 3; l++)
                #pragma unroll
                for (int i = 0; i < 2; i++)
                    wmma::load_matrix_sync(fa[l][i],
                        st + l * G1_TILE + kk * TP + wm * 32 + i * 16, TP);
            #pragma unroll
            for (int l = 0; l < 3; l++)
                #pragma unroll
                for (int j = 0; j < 2; j++)
                    wmma::load_matrix_sync(fb[l][j],
                        st + (3 + l) * G1_TILE + kk * TP + wn * 32 + j * 16, TP);
            #pragma unroll
            for (int i = 0; i < 2; i++)
                #pragma unroll
                for (int j = 0; j < 2; j++) {
                    wmma::mma_sync(fc[i][j], fa[0][i], fb[0][j], fc[i][j]);
                    wmma::mma_sync(fc[i][j], fa[0][i], fb[1][j], fc[i][j]);
                    wmma::mma_sync(fc[i][j], fa[1][i], fb[0][j], fc[i][j]);
                    wmma::mma_sync(fc[i][j], fa[0][i], fb[2][j], fc[i][j]);
                    wmma::mma_sync(fc[i][j], fa[2][i], fb[0][j], fc[i][j]);
                    wmma::mma_sync(fc[i][j], fa[1][i], fb[1][j], fc[i][j]);
                }
        }
        __syncthreads();
    }

    // epilogue via smem (reuse pipeline buffers): 128x128 fp32 tile
    float* sc = (float*)dsm;
    #pragma unroll
    for (int i = 0; i < 2; i++)
        #pragma unroll
        for (int j = 0; j < 2; j++)
            wmma::store_matrix_sync(sc + (size_t)(wm * 32 + i * 16) * 128 + wn * 32 + j * 16,
                                    fc[i][j], 128, wmma::mem_row_major);
    __syncthreads();

    // coalesced p store
    float* C = p + ((size_t)b * THW + t0) * HW + q0;
    #pragma unroll
    for (int l = 0; l < 8; l++) {
        int i = tid + l * 512;                   // 0..4095 float4
        int row = i >> 5, col = (i & 31) << 2;
        *(float4*)(C + (size_t)row * HW + col) = *(float4*)(sc + row * 128 + col);
    }

    // fused argmax partial: 4 threads per row (32 q each)
    {
        int row = tid >> 2, h = tid & 3;
        const float* r = sc + row * 128 + h * 32;
        float bv = r[0];
        int bj = 0;
        #pragma unroll 8
        for (int k = 1; k < 32; k++)
            if (r[k] > bv) { bv = r[k]; bj = k; }
        int gq = q0 + h * 32 + bj;
        #pragma unroll
        for (int off = 2; off > 0; off >>= 1) {
            float ov = __shfl_xor_sync(~0u, bv, off);
            int   oi = __shfl_xor_sync(~0u, gq, off);
            if (ov > bv || (ov == bv && oi < gq)) { bv = ov; gq = oi; }
        }
        if (h == 0)
            g_amax[((size_t)b * THW + t0 + row) * 8 + blockIdx.x] =
                make_float2(bv, (float)gq);
    }
}

// reduce 8 tile-partials per row -> gaussian center
__global__ void __launch_bounds__(256) argmax_final()
{
    int r = blockIdx.x * 256 + threadIdx.x;
    if (r >= B_ * THW) return;
    const float2* a = g_amax + (size_t)r * 8;
    float bv = a[0].x;
    int bi = (int)a[0].y;
    #pragma unroll
    for (int k = 1; k < 8; k++) {
        float2 v = a[k];
        if (v.x > bv) { bv = v.x; bi = (int)v.y; }
    }
    g_center[r] = make_float2((float)(bi & 31), (float)(bi >> 5));
}

// ============================================================
// exp + transpose: e^T bf16 hi/lo + partial sums (p preserved)
// ============================================================
__global__ void __launch_bounds__(256) exp_t_kernel(const float* __restrict__ p)
{
    __shared__ float tile[128][33];
    __shared__ float ssum[8][32];
    const int b = blockIdx.z, t0 = blockIdx.y * 128, q0 = blockIdx.x * 32;
    const int tid = threadIdx.x, tx = tid & 31, ty = tid >> 5;
    const float qx = (float)((q0 + tx) & 31), qy = (float)((q0 + tx) >> 5);
    const float* pc = p + ((size_t)b * THW + t0) * HW + q0 + tx;
    const float2* cen = g_center + (size_t)b * THW + t0;
    float s = 0.f;
    #pragma unroll 4
    for (int r = 0; r < 16; r++) {
        int t = ty * 16 + r;
        float2 c = cen[t];
        float dx = qx - c.x, dy = qy - c.y;
        float v = __expf(pc[(size_t)t * HW] - (dx * dx + dy * dy) * INV2SIG2);
        tile[t][tx] = v;
        s += v;
    }
    ssum[ty][tx] = s;
    __syncthreads();
    if (ty == 0) {
        float a = 0.f;
        #pragma unroll
        for (int k = 0; k < 8; k++) a += ssum[k][tx];
        g_part[((size_t)b * NCHUNK + blockIdx.y) * HW + q0 + tx] = a;
    }
    const int qq = tid & 31, seg = tid >> 5;
    uint32_t hi[8], lo[8];
    #pragma unroll
    for (int k = 0; k < 8; k++) {
        float v0 = tile[seg * 16 + 2 * k][qq], v1 = tile[seg * 16 + 2 * k + 1][qq];
        __nv_bfloat16 h0 = __float2bfloat16(v0), h1 = __float2bfloat16(v1);
        hi[k] = ((uint32_t)*(uint16_t*)&h1 << 16) | *(uint16_t*)&h0;
        __nv_bfloat16 l0 = __float2bfloat16(v0 - __bfloat162float(h0));
        __nv_bfloat16 l1 = __float2bfloat16(v1 - __bfloat162float(h1));
        lo[k] = ((uint32_t)*(uint16_t*)&l1 << 16) | *(uint16_t*)&l0;
    }
    size_t o = ((size_t)b * HW + q0 + qq) * THW + t0 + seg * 16;
    *(uint4*)(g_ehi + o)     = make_uint4(hi[0], hi[1], hi[2], hi[3]);
    *(uint4*)(g_ehi + o + 8) = make_uint4(hi[4], hi[5], hi[6], hi[7]);
    *(uint4*)(g_elo + o)     = make_uint4(lo[0], lo[1], lo[2], lo[3]);
    *(uint4*)(g_elo + o + 8) = make_uint4(lo[4], lo[5], lo[6], lo[7]);
}

__global__ void __launch_bounds__(256) inv_kernel()
{
    int i = blockIdx.x * 256 + threadIdx.x;
    int b = i >> 10, q = i & 1023;
    float s = 0.f;
    #pragma unroll
    for (int c = 0; c < NCHUNK; c++) s += g_part[((size_t)b * NCHUNK + c) * HW + q];
    g_inv[i] = 1.0f / s;
}

// ============================================================
// WMMA bf16 GEMM2 with cp.async 3-stage pipeline
// ============================================================
#define KP 40
#define NSTAGE 3
#define TILE_ELEMS (128 * KP)
#define STAGE_ELEMS (4 * TILE_ELEMS)
#define SMEM_DYN (NSTAGE * STAGE_ELEMS * 2)

__global__ void __launch_bounds__(256) gemm2_wmma()
{
    extern __shared__ __nv_bfloat16 dsm[];
    const int b = blockIdx.z;
    const int q0 = blockIdx.x * 128, o0 = blockIdx.y * 128;
    const int tid = threadIdx.x, wid = tid >> 5;
    const int wm = wid & 3, wn = wid >> 2;

    const __nv_bfloat16* Ah = g_mohi + ((size_t)b * DO + o0) * THW;
    const __nv_bfloat16* Al = g_molo + ((size_t)b * DO + o0) * THW;
    const __nv_bfloat16* Bh = g_ehi  + ((size_t)b * HW + q0) * THW;
    const __nv_bfloat16* Bl = g_elo  + ((size_t)b * HW + q0) * THW;

    const uint32_t sbase = (uint32_t)__cvta_generic_to_shared(dsm);

    auto load_stage = [&](int slot, int kc) {
        uint32_t sb = sbase + (uint32_t)slot * (STAGE_ELEMS * 2);
        #pragma unroll
        for (int l = 0; l < 8; l++) {
            int idx = tid + l * 256;
            int arr = idx >> 9, rem = idx & 511;
            int row = rem >> 2, ch = rem & 3;
            const __nv_bfloat16* src =
                (arr == 0 ? Ah : arr == 1 ? Al : arr == 2 ? Bh : Bl);
            cp16(sb + (uint32_t)arr * (TILE_ELEMS * 2) + row * (KP * 2) + ch * 16,
                 src + (size_t)row * THW + kc + ch * 8);
        }
    };

    wmma::fragment<wmma::accumulator, 16, 16, 16, float> fc[2][4];
    #pragma unroll
    for (int i = 0; i < 2; i++)
        #pragma unroll
        for (int j = 0; j < 4; j++) wmma::fill_fragment(fc[i][j], 0.f);

    const int NC = THW / 32;

    #pragma unroll
    for (int s = 0; s < NSTAGE - 1; s++) {
        load_stage(s, s * 32);
        CP_COMMIT();
    }

    for (int c = 0; c < NC; c++) {
        CP_WAIT(NSTAGE - 2);
        __syncthreads();
        int nl = c + NSTAGE - 1;
        if (nl < NC) load_stage(nl % NSTAGE, nl * 32);
        CP_COMMIT();

        __nv_bfloat16* st  = dsm + (size_t)(c % NSTAGE) * STAGE_ELEMS;
        __nv_bfloat16* tAh = st;
        __nv_bfloat16* tAl = st + TILE_ELEMS;
        __nv_bfloat16* tBh = st + 2 * TILE_ELEMS;
        __nv_bfloat16* tBl = st + 3 * TILE_ELEMS;

        #pragma unroll
        for (int kk = 0; kk < 32; kk += 16) {
            wmma::fragment<wmma::matrix_a, 16, 16, 16, __nv_bfloat16, wmma::row_major> fah[2], fal[2];
            wmma::fragment<wmma::matrix_b, 16, 16, 16, __nv_bfloat16, wmma::col_major> fbh[4], fbl[4];
            #pragma unroll
            for (int i = 0; i < 2; i++) {
                wmma::load_matrix_sync(fah[i], tAh + (wm * 32 + i * 16) * KP + kk, KP);
                wmma::load_matrix_sync(fal[i], tAl + (wm * 32 + i * 16) * KP + kk, KP);
            }
            #pragma unroll
            for (int j = 0; j < 4; j++) {
                wmma::load_matrix_sync(fbh[j], tBh + (wn * 64 + j * 16) * KP + kk, KP);
                wmma::load_matrix_sync(fbl[j], tBl + (wn * 64 + j * 16) * KP + kk, KP);
            }
            #pragma unroll
            for (int i = 0; i < 2; i++)
                #pragma unroll
                for (int j = 0; j < 4; j++) {
                    wmma::mma_sync(fc[i][j], fah[i], fbh[j], fc[i][j]);
                    wmma::mma_sync(fc[i][j], fah[i], fbl[j], fc[i][j]);
                    wmma::mma_sync(fc[i][j], fal[i], fbh[j], fc[i][j]);
                }
        }
    }
    CP_WAIT(0);

    float* C = g_c + ((size_t)b * DO + o0) * HW + q0;
    #pragma unroll
    for (int i = 0; i < 2; i++)
        #pragma unroll
        for (int j = 0; j < 4; j++)
            wmma::store_matrix_sync(C + (size_t)(wm * 32 + i * 16) * HW + wn * 64 + j * 16,
                                    fc[i][j], HW, wmma::mem_row_major);
}

// apply inv -> out[:, :Do]
__global__ void __launch_bounds__(256) combine_kernel(float* __restrict__ out)
{
    const size_t n4 = (size_t)B_ * DO * HW / 4;
    size_t i = (size_t)blockIdx.x * 256 + threadIdx.x;
    if (i >= n4) return;
    float4 a = ((const float4*)g_c)[i];
    size_t q4 = i & 255;
    size_t b  = i / ((size_t)DO * HW / 4);
    float4 inv = ((const float4*)g_inv)[b * 256 + q4];
    float4 v = make_float4(a.x * inv.x, a.y * inv.y, a.z * inv.z, a.w * inv.w);
    size_t r = i - b * ((size_t)DO * HW / 4);
    ((float4*)out)[b * ((size_t)2 * DO * HW / 4) + r] = v;
}

__global__ void __launch_bounds__(256) copy_qout_kernel(
    const float* __restrict__ q_out, float* __restrict__ out)
{
    const size_t per_b4 = (size_t)DO * HW / 4;
    size_t i = (size_t)blockIdx.x * 256 + threadIdx.x;
    if (i >= (size_t)B_ * per_b4) return;
    size_t b = i / per_b4, r = i - b * per_b4;
    ((float4*)out)[b * 2 * per_b4 + per_b4 + r] = ((const float4*)q_out)[i];
}

// p_w fp32 output: recompute exp from preserved p, apply inv
__global__ void __launch_bounds__(256) pw_kernel(const float* __restrict__ p,
                                                 float* __restrict__ dst)
{
    const size_t total4 = (size_t)B_ * THW * HW / 4;
    const size_t stride = (size_t)gridDim.x * 256;
    for (size_t i = (size_t)blockIdx.x * 256 + threadIdx.x; i < total4; i += stride) {
        float4 v = ((const float4*)p)[i];
        size_t bt = i >> 8;
        int q4 = (int)(i & 255);
        int qbase = q4 * 4;
        size_t b = bt / THW;
        float2 c = g_center[bt];
        float4 inv = ((const float4*)g_inv)[b * 256 + q4];
        float qy = (float)(qbase >> 5);
        float dy2 = (qy - c.y) * (qy - c.y);
        float4 r;
        { float dx = (float)((qbase + 0) & 31) - c.x; r.x = __expf(v.x - (dx*dx + dy2) * INV2SIG2) * inv.x; }
        { float dx = (float)((qbase + 1) & 31) - c.x; r.y = __expf(v.y - (dx*dx + dy2) * INV2SIG2) * inv.y; }
        { float dx = (float)((qbase + 2) & 31) - c.x; r.z = __expf(v.z - (dx*dx + dy2) * INV2SIG2) * inv.z; }
        { float dx = (float)((qbase + 3) & 31) - c.x; r.w = __expf(v.w - (dx*dx + dy2) * INV2SIG2) * inv.w; }
        ((float4*)dst)[i] = r;
    }
}

// ============================================================
extern "C" void kernel_launch(void* const* d_in, const int* in_sizes, int n_in,
                              void* d_out, int out_size)
{
    const float* m_in  = (const float*)d_in[0];
    const float* m_out = (const float*)d_in[1];
    const float* q_in  = (const float*)d_in[2];
    const float* q_out = (const float*)d_in[3];
    float* out = (float*)d_out;

    float* p = nullptr;
    cudaGetSymbolAddress((void**)&p, g_p);
    __nv_bfloat16 *mi0, *mi1, *mi2, *qi0, *qi1, *qi2;
    cudaGetSymbolAddress((void**)&mi0, g_mi0);
    cudaGetSymbolAddress((void**)&mi1, g_mi1);
    cudaGetSymbolAddress((void**)&mi2, g_mi2);
    cudaGetSymbolAddress((void**)&qi0, g_qi0);
    cudaGetSymbolAddress((void**)&qi1, g_qi1);
    cudaGetSymbolAddress((void**)&qi2, g_qi2);

    cudaFuncSetAttribute(gemm1_wmma, cudaFuncAttributeMaxDynamicSharedMemorySize, G1_SMEM);
    cudaFuncSetAttribute(gemm2_wmma, cudaFuncAttributeMaxDynamicSharedMemorySize, SMEM_DYN);

    // 0) split mi (3 limbs), qi*SCALE (3 limbs), mo (2 limbs)
    split3_kernel<<<2048, 256>>>(m_in, mi0, mi1, mi2, (size_t)B_ * DE * THW / 4, 1.0f);
    split3_kernel<<<512, 256>>>(q_in, qi0, qi1, qi2, (size_t)B_ * DE * HW / 4, SCALE);
    split_kernel<<<4096, 256>>>(m_out);

    // 1) p = mi^T (qi*SCALE) via WMMA 3-limb + fused argmax partials
    dim3 g1(HW / 128, THW / 128, B_);   // (8, 80, 4)
    gemm1_wmma<<<g1, 512, G1_SMEM>>>(p);

    // 2) argmax final reduce -> centers
    argmax_final<<<(B_ * THW + 255) / 256, 256>>>();

    // 3) exp + transpose + partial sums
    dim3 g3(HW / 32, THW / 128, B_);
    exp_t_kernel<<<g3, 256>>>(p);

    // 4) inv
    inv_kernel<<<(B_ * HW) / 256, 256>>>();

    // 5) WMMA bf16 GEMM2, cp.async pipelined
    dim3 g4(HW / 128, DO / 128, B_);
    gemm2_wmma<<<g4, 256, SMEM_DYN>>>();

    // 6) normalize -> out[:, :Do]
    combine_kernel<<<(B_ * DO * HW / 4 + 255) / 256, 256>>>(out);

    // 7) out[:, Do:] = q_out
    copy_qout_kernel<<<(B_ * DO * HW / 4 + 255) / 256, 256>>>(q_out, out);

    // 8) optional p_w output
    const size_t memout = (size_t)B_ * 2 * DO * HW;
    const size_t pw     = (size_t)B_ * THW * HW;
    if ((size_t)out_size >= memout + pw)
        pw_kernel<<<4096, 256>>>(p, out + memout);
}

// round 9
// speedup vs baseline: 1.0699x; 1.0699x over previous
#include <cuda_runtime.h>
#include <cuda_bf16.h>
#include <mma.h>
#include <cstdint>
#include <math.h>

using namespace nvcuda;

#define B_    4
#define DE    128
#define DO    512
#define THW   10240
#define HW    1024
#define NCHUNK 80
#define SCALE 0.08838834764831845f
#define INV2SIG2 (1.0f/18.0f)

// ---------------- device scratch ----------------
__device__ float         g_p[(size_t)B_ * THW * HW];       // p fp32 (preserved)
__device__ __nv_bfloat16 g_ehi[(size_t)B_ * HW * THW];     // e^T [b][q][t] hi
__device__ __nv_bfloat16 g_elo[(size_t)B_ * HW * THW];
__device__ __nv_bfloat16 g_mohi[(size_t)B_ * DO * THW];
__device__ __nv_bfloat16 g_molo[(size_t)B_ * DO * THW];
__device__ __nv_bfloat16 g_mi0[(size_t)B_ * DE * THW];     // mi 3 limbs [b][d][t]
__device__ __nv_bfloat16 g_mi1[(size_t)B_ * DE * THW];
__device__ __nv_bfloat16 g_mi2[(size_t)B_ * DE * THW];
__device__ __nv_bfloat16 g_qi0[(size_t)B_ * DE * HW];      // qi*SCALE 3 limbs [b][d][q]
__device__ __nv_bfloat16 g_qi1[(size_t)B_ * DE * HW];
__device__ __nv_bfloat16 g_qi2[(size_t)B_ * DE * HW];
__device__ float         g_c[(size_t)B_ * DO * HW];        // raw GEMM2 result
__device__ float2        g_center[B_ * THW];
__device__ float2        g_amax[(size_t)B_ * THW * 8];     // per-qtile argmax partials
__device__ float         g_part[(size_t)B_ * NCHUNK * HW];
__device__ float         g_inv[B_ * HW];

__device__ __forceinline__ void cp16(uint32_t sa, const void* g) {
    asm volatile("cp.async.cg.shared.global [%0], [%1], 16;" :: "r"(sa), "l"(g));
}
#define CP_COMMIT() asm volatile("cp.async.commit_group;" ::: "memory")
#define CP_WAIT(n)  asm volatile("cp.async.wait_group %0;" :: "n"(n) : "memory")

// ============================================================
// split fp32 -> 3 bf16 limbs (optional scale)
// ============================================================
__global__ void __launch_bounds__(256) split3_kernel(
    const float* __restrict__ in, __nv_bfloat16* __restrict__ o0,
    __nv_bfloat16* __restrict__ o1, __nv_bfloat16* __restrict__ o2,
    size_t n4, float scale)
{
    const size_t stride = (size_t)gridDim.x * 256;
    for (size_t i = (size_t)blockIdx.x * 256 + threadIdx.x; i < n4; i += stride) {
        float4 v = ((const float4*)in)[i];
        v.x *= scale; v.y *= scale; v.z *= scale; v.w *= scale;
        float f[4] = {v.x, v.y, v.z, v.w};
        uint16_t l0[4], l1[4], l2[4];
        #pragma unroll
        for (int k = 0; k < 4; k++) {
            __nv_bfloat16 h0 = __float2bfloat16(f[k]);
            float r = f[k] - __bfloat162float(h0);
            __nv_bfloat16 h1 = __float2bfloat16(r);
            float r2 = r - __bfloat162float(h1);
            __nv_bfloat16 h2 = __float2bfloat16(r2);
            l0[k] = *(uint16_t*)&h0; l1[k] = *(uint16_t*)&h1; l2[k] = *(uint16_t*)&h2;
        }
        ((uint2*)o0)[i] = make_uint2(l0[0] | ((uint32_t)l0[1] << 16), l0[2] | ((uint32_t)l0[3] << 16));
        ((uint2*)o1)[i] = make_uint2(l1[0] | ((uint32_t)l1[1] << 16), l1[2] | ((uint32_t)l1[3] << 16));
        ((uint2*)o2)[i] = make_uint2(l2[0] | ((uint32_t)l2[1] << 16), l2[2] | ((uint32_t)l2[3] << 16));
    }
}

// mo fp32 -> bf16 hi/lo (2 limbs, for GEMM2)
__global__ void __launch_bounds__(256) split_kernel(const float* __restrict__ in)
{
    const size_t n4 = (size_t)B_ * DO * THW / 4;
    const size_t stride = (size_t)gridDim.x * 256;
    for (size_t i = (size_t)blockIdx.x * 256 + threadIdx.x; i < n4; i += stride) {
        float4 v = ((const float4*)in)[i];
        __nv_bfloat16 h0 = __float2bfloat16(v.x), h1 = __float2bfloat16(v.y);
        __nv_bfloat16 h2 = __float2bfloat16(v.z), h3 = __float2bfloat16(v.w);
        __nv_bfloat162* H = (__nv_bfloat162*)g_mohi;
        __nv_bfloat162* L = (__nv_bfloat162*)g_molo;
        H[2*i]   = __halves2bfloat162(h0, h1);
        H[2*i+1] = __halves2bfloat162(h2, h3);
        L[2*i]   = __halves2bfloat162(__float2bfloat16(v.x - __bfloat162float(h0)),
                                      __float2bfloat16(v.y - __bfloat162float(h1)));
        L[2*i+1] = __halves2bfloat162(__float2bfloat16(v.z - __bfloat162float(h2)),
                                      __float2bfloat16(v.w - __bfloat162float(h3)));
    }
}

// ============================================================
// WMMA bf16 GEMM1 (3-limb, 6 passes): p = (mi)^T (qi*SCALE)
// 256 threads / 8 warps (4x2), warp tile 32(t) x 64(q)
// restructured inner loop (<=128 regs) -> 2 CTAs/SM
// ============================================================
#define TP 136
#define G1_TILE (32 * TP)
#define G1_STAGE (6 * G1_TILE)
#define G1_SMEM (2 * G1_STAGE * 2)              // 104448 bytes

__global__ void __launch_bounds__(256, 2) gemm1_wmma(float* __restrict__ p)
{
    extern __shared__ __nv_bfloat16 dsm[];
    const int b = blockIdx.z;
    const int q0 = blockIdx.x * 128, t0 = blockIdx.y * 128;
    const int tid = threadIdx.x, wid = tid >> 5;
    const int wm = wid & 3, wn = wid >> 2;       // warp tile 32(t) x 64(q)

    const __nv_bfloat16* A0 = g_mi0 + (size_t)b * DE * THW;
    const __nv_bfloat16* A1 = g_mi1 + (size_t)b * DE * THW;
    const __nv_bfloat16* A2 = g_mi2 + (size_t)b * DE * THW;
    const __nv_bfloat16* B0 = g_qi0 + (size_t)b * DE * HW;
    const __nv_bfloat16* B1 = g_qi1 + (size_t)b * DE * HW;
    const __nv_bfloat16* B2 = g_qi2 + (size_t)b * DE * HW;

    const uint32_t sbase = (uint32_t)__cvta_generic_to_shared(dsm);

    auto load_stage = [&](int slot, int k0) {
        uint32_t sb = sbase + (uint32_t)slot * (G1_STAGE * 2);
        #pragma unroll
        for (int l = 0; l < 12; l++) {
            int idx = tid + l * 256;             // 0..3071
            int arr = idx >> 9, rem = idx & 511;
            int row = rem >> 4, col = rem & 15;  // row<32 (d), col*8 elems
            const __nv_bfloat16* src;
            if (arr < 3) {
                src = (arr == 0 ? A0 : arr == 1 ? A1 : A2)
                      + (size_t)(k0 + row) * THW + t0 + col * 8;
            } else {
                src = (arr == 3 ? B0 : arr == 4 ? B1 : B2)
                      + (size_t)(k0 + row) * HW + q0 + col * 8;
            }
            cp16(sb + (uint32_t)arr * (G1_TILE * 2) + row * (TP * 2) + col * 16, src);
        }
    };

    wmma::fragment<wmma::accumulator, 16, 16, 16, float> fc[2][4];
    #pragma unroll
    for (int i = 0; i < 2; i++)
        #pragma unroll
        for (int j = 0; j < 4; j++) wmma::fill_fragment(fc[i][j], 0.f);

    const int NC = DE / 32;   // 4
    load_stage(0, 0);
    CP_COMMIT();

    for (int c = 0; c < NC; c++) {
        if (c + 1 < NC) { load_stage((c + 1) & 1, (c + 1) * 32); CP_COMMIT(); }
        if (c + 1 < NC) CP_WAIT(1); else CP_WAIT(0);
        __syncthreads();

        __nv_bfloat16* st = dsm + (size_t)(c & 1) * G1_STAGE;
        #pragma unroll
        for (int kk = 0; kk < 32; kk += 16) {
            // hold all 6 A-limb fragments
            wmma::fragment<wmma::matrix_a, 16, 16, 16, __nv_bfloat16, wmma::col_major> fa[3][2];
            #pragma unroll
            for (int l = 0; l < 3; l++)
                #pragma unroll
                for (int i = 0; i < 2; i++)
                    wmma::load_matrix_sync(fa[l][i],
                        st + l * G1_TILE + kk * TP + wm * 32 + i * 16, TP);
            // B limb 0: x A0, A1, A2
            {
                wmma::fragment<wmma::matrix_b, 16, 16, 16, __nv_bfloat16, wmma::row_major> fb[4];
                #pragma unroll
                for (int j = 0; j < 4; j++)
                    wmma::load_matrix_sync(fb[j],
                        st + 3 * G1_TILE + kk * TP + wn * 64 + j * 16, TP);
                #pragma unroll
                for (int i = 0; i < 2; i++)
                    #pragma unroll
                    for (int j = 0; j < 4; j++) {
                        wmma::mma_sync(fc[i][j], fa[0][i], fb[j], fc[i][j]);
                        wmma::mma_sync(fc[i][j], fa[1][i], fb[j], fc[i][j]);
                        wmma::mma_sync(fc[i][j], fa[2][i], fb[j], fc[i][j]);
                    }
            }
            // B limb 1: x A0, A1
            {
                wmma::fragment<wmma::matrix_b, 16, 16, 16, __nv_bfloat16, wmma::row_major> fb[4];
                #pragma unroll
                for (int j = 0; j < 4; j++)
                    wmma::load_matrix_sync(fb[j],
                        st + 4 * G1_TILE + kk * TP + wn * 64 + j * 16, TP);
                #pragma unroll
                for (int i = 0; i < 2; i++)
                    #pragma unroll
                    for (int j = 0; j < 4; j++) {
                        wmma::mma_sync(fc[i][j], fa[0][i], fb[j], fc[i][j]);
                        wmma::mma_sync(fc[i][j], fa[1][i], fb[j], fc[i][j]);
                    }
            }
            // B limb 2: x A0
            {
                wmma::fragment<wmma::matrix_b, 16, 16, 16, __nv_bfloat16, wmma::row_major> fb[4];
                #pragma unroll
                for (int j = 0; j < 4; j++)
                    wmma::load_matrix_sync(fb[j],
                        st + 5 * G1_TILE + kk * TP + wn * 64 + j * 16, TP);
                #pragma unroll
                for (int i = 0; i < 2; i++)
                    #pragma unroll
                    for (int j = 0; j < 4; j++)
                        wmma::mma_sync(fc[i][j], fa[0][i], fb[j], fc[i][j]);
            }
        }
        __syncthreads();
    }

    // epilogue via smem: 128x128 fp32 tile
    float* sc = (float*)dsm;
    #pragma unroll
    for (int i = 0; i < 2; i++)
        #pragma unroll
        for (int j = 0; j < 4; j++)
            wmma::store_matrix_sync(sc + (size_t)(wm * 32 + i * 16) * 128 + wn * 64 + j * 16,
                                    fc[i][j], 128, wmma::mem_row_major);
    __syncthreads();

    // coalesced p store
    float* C = p + ((size_t)b * THW + t0) * HW + q0;
    #pragma unroll
    for (int l = 0; l < 16; l++) {
        int i = tid + l * 256;                   // 0..4095 float4
        int row = i >> 5, col = (i & 31) << 2;
        *(float4*)(C + (size_t)row * HW + col) = *(float4*)(sc + row * 128 + col);
    }

    // fused argmax partial: 2 threads per row (64 q each)
    {
        int row = tid >> 1, h = tid & 1;
        const float* r = sc + row * 128 + h * 64;
        float bv = r[0];
        int bj = 0;
        #pragma unroll 8
        for (int k = 1; k < 64; k++)
            if (r[k] > bv) { bv = r[k]; bj = k; }
        int gq = q0 + h * 64 + bj;
        float ov = __shfl_xor_sync(~0u, bv, 1);
        int   oi = __shfl_xor_sync(~0u, gq, 1);
        if (ov > bv || (ov == bv && oi < gq)) { bv = ov; gq = oi; }
        if (h == 0)
            g_amax[((size_t)b * THW + t0 + row) * 8 + blockIdx.x] =
                make_float2(bv, (float)gq);
    }
}

// reduce 8 tile-partials per row -> gaussian center
__global__ void __launch_bounds__(256) argmax_final()
{
    int r = blockIdx.x * 256 + threadIdx.x;
    if (r >= B_ * THW) return;
    const float2* a = g_amax + (size_t)r * 8;
    float bv = a[0].x;
    int bi = (int)a[0].y;
    #pragma unroll
    for (int k = 1; k < 8; k++) {
        float2 v = a[k];
        if (v.x > bv) { bv = v.x; bi = (int)v.y; }
    }
    g_center[r] = make_float2((float)(bi & 31), (float)(bi >> 5));
}

// ============================================================
// exp + transpose: e^T bf16 hi/lo + partial sums (p preserved)
// ============================================================
__global__ void __launch_bounds__(256) exp_t_kernel(const float* __restrict__ p)
{
    __shared__ float tile[128][33];
    __shared__ float ssum[8][32];
    const int b = blockIdx.z, t0 = blockIdx.y * 128, q0 = blockIdx.x * 32;
    const int tid = threadIdx.x, tx = tid & 31, ty = tid >> 5;
    const float qx = (float)((q0 + tx) & 31), qy = (float)((q0 + tx) >> 5);
    const float* pc = p + ((size_t)b * THW + t0) * HW + q0 + tx;
    const float2* cen = g_center + (size_t)b * THW + t0;
    float s = 0.f;
    #pragma unroll 4
    for (int r = 0; r < 16; r++) {
        int t = ty * 16 + r;
        float2 c = cen[t];
        float dx = qx - c.x, dy = qy - c.y;
        float v = __expf(pc[(size_t)t * HW] - (dx * dx + dy * dy) * INV2SIG2);
        tile[t][tx] = v;
        s += v;
    }
    ssum[ty][tx] = s;
    __syncthreads();
    if (ty == 0) {
        float a = 0.f;
        #pragma unroll
        for (int k = 0; k < 8; k++) a += ssum[k][tx];
        g_part[((size_t)b * NCHUNK + blockIdx.y) * HW + q0 + tx] = a;
    }
    const int qq = tid & 31, seg = tid >> 5;
    uint32_t hi[8], lo[8];
    #pragma unroll
    for (int k = 0; k < 8; k++) {
        float v0 = tile[seg * 16 + 2 * k][qq], v1 = tile[seg * 16 + 2 * k + 1][qq];
        __nv_bfloat16 h0 = __float2bfloat16(v0), h1 = __float2bfloat16(v1);
        hi[k] = ((uint32_t)*(uint16_t*)&h1 << 16) | *(uint16_t*)&h0;
        __nv_bfloat16 l0 = __float2bfloat16(v0 - __bfloat162float(h0));
        __nv_bfloat16 l1 = __float2bfloat16(v1 - __bfloat162float(h1));
        lo[k] = ((uint32_t)*(uint16_t*)&l1 << 16) | *(uint16_t*)&l0;
    }
    size_t o = ((size_t)b * HW + q0 + qq) * THW + t0 + seg * 16;
    *(uint4*)(g_ehi + o)     = make_uint4(hi[0], hi[1], hi[2], hi[3]);
    *(uint4*)(g_ehi + o + 8) = make_uint4(hi[4], hi[5], hi[6], hi[7]);
    *(uint4*)(g_elo + o)     = make_uint4(lo[0], lo[1], lo[2], lo[3]);
    *(uint4*)(g_elo + o + 8) = make_uint4(lo[4], lo[5], lo[6], lo[7]);
}

__global__ void __launch_bounds__(256) inv_kernel()
{
    int i = blockIdx.x * 256 + threadIdx.x;
    int b = i >> 10, q = i & 1023;
    float s = 0.f;
    #pragma unroll
    for (int c = 0; c < NCHUNK; c++) s += g_part[((size_t)b * NCHUNK + c) * HW + q];
    g_inv[i] = 1.0f / s;
}

// ============================================================
// WMMA bf16 GEMM2, 2-stage cp.async, <=128 regs -> 2 CTAs/SM
// ============================================================
#define KP 40
#define NSTAGE 2
#define TILE_ELEMS (128 * KP)
#define STAGE_ELEMS (4 * TILE_ELEMS)
#define SMEM_DYN (NSTAGE * STAGE_ELEMS * 2)     // 81920 bytes

__global__ void __launch_bounds__(256, 2) gemm2_wmma()
{
    extern __shared__ __nv_bfloat16 dsm[];
    const int b = blockIdx.z;
    const int q0 = blockIdx.x * 128, o0 = blockIdx.y * 128;
    const int tid = threadIdx.x, wid = tid >> 5;
    const int wm = wid & 3, wn = wid >> 2;

    const __nv_bfloat16* Ah = g_mohi + ((size_t)b * DO + o0) * THW;
    const __nv_bfloat16* Al = g_molo + ((size_t)b * DO + o0) * THW;
    const __nv_bfloat16* Bh = g_ehi  + ((size_t)b * HW + q0) * THW;
    const __nv_bfloat16* Bl = g_elo  + ((size_t)b * HW + q0) * THW;

    const uint32_t sbase = (uint32_t)__cvta_generic_to_shared(dsm);

    auto load_stage = [&](int slot, int kc) {
        uint32_t sb = sbase + (uint32_t)slot * (STAGE_ELEMS * 2);
        #pragma unroll
        for (int l = 0; l < 8; l++) {
            int idx = tid + l * 256;
            int arr = idx >> 9, rem = idx & 511;
            int row = rem >> 2, ch = rem & 3;
            const __nv_bfloat16* src =
                (arr == 0 ? Ah : arr == 1 ? Al : arr == 2 ? Bh : Bl);
            cp16(sb + (uint32_t)arr * (TILE_ELEMS * 2) + row * (KP * 2) + ch * 16,
                 src + (size_t)row * THW + kc + ch * 8);
        }
    };

    wmma::fragment<wmma::accumulator, 16, 16, 16, float> fc[2][4];
    #pragma unroll
    for (int i = 0; i < 2; i++)
        #pragma unroll
        for (int j = 0; j < 4; j++) wmma::fill_fragment(fc[i][j], 0.f);

    const int NC = THW / 32;   // 320

    load_stage(0, 0);
    CP_COMMIT();

    for (int c = 0; c < NC; c++) {
        CP_WAIT(0);
        __syncthreads();
        if (c + 1 < NC) { load_stage((c + 1) & 1, (c + 1) * 32); CP_COMMIT(); }

        __nv_bfloat16* st  = dsm + (size_t)(c & 1) * STAGE_ELEMS;
        __nv_bfloat16* tAh = st;
        __nv_bfloat16* tAl = st + TILE_ELEMS;
        __nv_bfloat16* tBh = st + 2 * TILE_ELEMS;
        __nv_bfloat16* tBl = st + 3 * TILE_ELEMS;

        #pragma unroll
        for (int kk = 0; kk < 32; kk += 16) {
            wmma::fragment<wmma::matrix_a, 16, 16, 16, __nv_bfloat16, wmma::row_major> fah[2], fal[2];
            #pragma unroll
            for (int i = 0; i < 2; i++) {
                wmma::load_matrix_sync(fah[i], tAh + (wm * 32 + i * 16) * KP + kk, KP);
                wmma::load_matrix_sync(fal[i], tAl + (wm * 32 + i * 16) * KP + kk, KP);
            }
            #pragma unroll
            for (int j = 0; j < 4; j++) {
                wmma::fragment<wmma::matrix_b, 16, 16, 16, __nv_bfloat16, wmma::col_major> fbh, fbl;
                wmma::load_matrix_sync(fbh, tBh + (wn * 64 + j * 16) * KP + kk, KP);
                wmma::load_matrix_sync(fbl, tBl + (wn * 64 + j * 16) * KP + kk, KP);
                #pragma unroll
                for (int i = 0; i < 2; i++) {
                    wmma::mma_sync(fc[i][j], fah[i], fbh, fc[i][j]);
                    wmma::mma_sync(fc[i][j], fah[i], fbl, fc[i][j]);
                    wmma::mma_sync(fc[i][j], fal[i], fbh, fc[i][j]);
                }
            }
        }
        __syncthreads();
    }

    float* C = g_c + ((size_t)b * DO + o0) * HW + q0;
    #pragma unroll
    for (int i = 0; i < 2; i++)
        #pragma unroll
        for (int j = 0; j < 4; j++)
            wmma::store_matrix_sync(C + (size_t)(wm * 32 + i * 16) * HW + wn * 64 + j * 16,
                                    fc[i][j], HW, wmma::mem_row_major);
}

// apply inv -> out[:, :Do]
__global__ void __launch_bounds__(256) combine_kernel(float* __restrict__ out)
{
    const size_t n4 = (size_t)B_ * DO * HW / 4;
    size_t i = (size_t)blockIdx.x * 256 + threadIdx.x;
    if (i >= n4) return;
    float4 a = ((const float4*)g_c)[i];
    size_t q4 = i & 255;
    size_t b  = i / ((size_t)DO * HW / 4);
    float4 inv = ((const float4*)g_inv)[b * 256 + q4];
    float4 v = make_float4(a.x * inv.x, a.y * inv.y, a.z * inv.z, a.w * inv.w);
    size_t r = i - b * ((size_t)DO * HW / 4);
    ((float4*)out)[b * ((size_t)2 * DO * HW / 4) + r] = v;
}

__global__ void __launch_bounds__(256) copy_qout_kernel(
    const float* __restrict__ q_out, float* __restrict__ out)
{
    const size_t per_b4 = (size_t)DO * HW / 4;
    size_t i = (size_t)blockIdx.x * 256 + threadIdx.x;
    if (i >= (size_t)B_ * per_b4) return;
    size_t b = i / per_b4, r = i - b * per_b4;
    ((float4*)out)[b * 2 * per_b4 + per_b4 + r] = ((const float4*)q_out)[i];
}

// p_w fp32 output from ehi/elo (no exp): transpose [b][q][t] -> [b][t][q], *inv
__global__ void __launch_bounds__(256) pw_t_kernel(float* __restrict__ dst)
{
    __shared__ float tile[32][129];
    __shared__ float sinv[32];
    const int b = blockIdx.z, t0 = blockIdx.y * 128, q0 = blockIdx.x * 32;
    const int tid = threadIdx.x;

    // read 32 q-rows x 128 t (coalesced along t)
    {
        int q = tid >> 3, seg = tid & 7;         // seg: 16 t elems
        size_t o = ((size_t)b * HW + q0 + q) * THW + t0 + seg * 16;
        uint4 h0 = *(const uint4*)(g_ehi + o);
        uint4 h1 = *(const uint4*)(g_ehi + o + 8);
        uint4 l0 = *(const uint4*)(g_elo + o);
        uint4 l1 = *(const uint4*)(g_elo + o + 8);
        const uint32_t hw_[8] = {h0.x, h0.y, h0.z, h0.w, h1.x, h1.y, h1.z, h1.w};
        const uint32_t lw_[8] = {l0.x, l0.y, l0.z, l0.w, l1.x, l1.y, l1.z, l1.w};
        #pragma unroll
        for (int k = 0; k < 8; k++) {
            __nv_bfloat162 hv = *(const __nv_bfloat162*)&hw_[k];
            __nv_bfloat162 lv = *(const __nv_bfloat162*)&lw_[k];
            tile[q][seg * 16 + 2 * k]     = __bfloat162float(hv.x) + __bfloat162float(lv.x);
            tile[q][seg * 16 + 2 * k + 1] = __bfloat162float(hv.y) + __bfloat162float(lv.y);
        }
    }
    if (tid < 32) sinv[tid] = g_inv[(size_t)b * HW + q0 + tid];
    __syncthreads();

    // write 128 t-rows x 32 q (2 threads per t-row, 16 q each)
    int t = tid >> 1, qs = (tid & 1) * 16;
    float* d = dst + ((size_t)b * THW + t0 + t) * HW + q0 + qs;
    #pragma unroll
    for (int k = 0; k < 16; k += 4) {
        float4 v = make_float4(tile[qs + k][t]     * sinv[qs + k],
                               tile[qs + k + 1][t] * sinv[qs + k + 1],
                               tile[qs + k + 2][t] * sinv[qs + k + 2],
                               tile[qs + k + 3][t] * sinv[qs + k + 3]);
        *(float4*)(d + k) = v;
    }
}

// ============================================================
extern "C" void kernel_launch(void* const* d_in, const int* in_sizes, int n_in,
                              void* d_out, int out_size)
{
    const float* m_in  = (const float*)d_in[0];
    const float* m_out = (const float*)d_in[1];
    const float* q_in  = (const float*)d_in[2];
    const float* q_out = (const float*)d_in[3];
    float* out = (float*)d_out;

    float* p = nullptr;
    cudaGetSymbolAddress((void**)&p, g_p);
    __nv_bfloat16 *mi0, *mi1, *mi2, *qi0, *qi1, *qi2;
    cudaGetSymbolAddress((void**)&mi0, g_mi0);
    cudaGetSymbolAddress((void**)&mi1, g_mi1);
    cudaGetSymbolAddress((void**)&mi2, g_mi2);
    cudaGetSymbolAddress((void**)&qi0, g_qi0);
    cudaGetSymbolAddress((void**)&qi1, g_qi1);
    cudaGetSymbolAddress((void**)&qi2, g_qi2);

    cudaFuncSetAttribute(gemm1_wmma, cudaFuncAttributeMaxDynamicSharedMemorySize, G1_SMEM);
    cudaFuncSetAttribute(gemm2_wmma, cudaFuncAttributeMaxDynamicSharedMemorySize, SMEM_DYN);

    // 0) split mi (3 limbs), qi*SCALE (3 limbs), mo (2 limbs)
    split3_kernel<<<2048, 256>>>(m_in, mi0, mi1, mi2, (size_t)B_ * DE * THW / 4, 1.0f);
    split3_kernel<<<512, 256>>>(q_in, qi0, qi1, qi2, (size_t)B_ * DE * HW / 4, SCALE);
    split_kernel<<<4096, 256>>>(m_out);

    // 1) p = mi^T (qi*SCALE) via WMMA 3-limb + fused argmax partials
    dim3 g1(HW / 128, THW / 128, B_);   // (8, 80, 4)
    gemm1_wmma<<<g1, 256, G1_SMEM>>>(p);

    // 2) argmax final reduce -> centers
    argmax_final<<<(B_ * THW + 255) / 256, 256>>>();

    // 3) exp + transpose + partial sums
    dim3 g3(HW / 32, THW / 128, B_);
    exp_t_kernel<<<g3, 256>>>(p);

    // 4) inv
    inv_kernel<<<(B_ * HW) / 256, 256>>>();

    // 5) WMMA bf16 GEMM2
    dim3 g4(HW / 128, DO / 128, B_);
    gemm2_wmma<<<g4, 256, SMEM_DYN>>>();

    // 6) normalize -> out[:, :Do]
    combine_kernel<<<(B_ * DO * HW / 4 + 255) / 256, 256>>>(out);

    // 7) out[:, Do:] = q_out
    copy_qout_kernel<<<(B_ * DO * HW / 4 + 255) / 256, 256>>>(q_out, out);

    // 8) optional p_w output (from ehi/elo, no exp)
    const size_t memout = (size_t)B_ * 2 * DO * HW;
    const size_t pw     = (size_t)B_ * THW * HW;
    if ((size_t)out_size >= memout + pw) {
        dim3 g5(HW / 32, THW / 128, B_);
        pw_t_kernel<<<g5, 256>>>(out + memout);
    }
}

// round 10
// speedup vs baseline: 1.1177x; 1.0447x over previous
#include <cuda_runtime.h>
#include <cuda_bf16.h>
#include <mma.h>
#include <cstdint>
#include <math.h>

using namespace nvcuda;

#define B_    4
#define DE    128
#define DO    512
#define THW   10240
#define HW    1024
#define NCHUNK 80
#define SCALE 0.08838834764831845f
#define INV2SIG2 (1.0f/18.0f)

// ---------------- device scratch ----------------
__device__ float         g_p[(size_t)B_ * THW * HW];       // p fp32 (preserved)
__device__ __nv_bfloat16 g_ehi[(size_t)B_ * HW * THW];     // e^T [b][q][t] hi
__device__ __nv_bfloat16 g_elo[(size_t)B_ * HW * THW];
__device__ __nv_bfloat16 g_mohi[(size_t)B_ * DO * THW];
__device__ __nv_bfloat16 g_molo[(size_t)B_ * DO * THW];
__device__ __nv_bfloat16 g_mi0[(size_t)B_ * DE * THW];     // mi 3 limbs [b][d][t]
__device__ __nv_bfloat16 g_mi1[(size_t)B_ * DE * THW];
__device__ __nv_bfloat16 g_mi2[(size_t)B_ * DE * THW];
__device__ __nv_bfloat16 g_qi0[(size_t)B_ * DE * HW];      // qi*SCALE 3 limbs [b][d][q]
__device__ __nv_bfloat16 g_qi1[(size_t)B_ * DE * HW];
__device__ __nv_bfloat16 g_qi2[(size_t)B_ * DE * HW];
__device__ float         g_cpart[(size_t)2 * B_ * DO * HW]; // split-K partials
__device__ float2        g_center[B_ * THW];
__device__ float2        g_amax[(size_t)B_ * THW * 8];     // per-qtile argmax partials
__device__ float         g_part[(size_t)B_ * NCHUNK * HW];
__device__ float         g_inv[B_ * HW];

__device__ __forceinline__ void cp16(uint32_t sa, const void* g) {
    asm volatile("cp.async.cg.shared.global [%0], [%1], 16;" :: "r"(sa), "l"(g));
}
#define CP_COMMIT() asm volatile("cp.async.commit_group;" ::: "memory")
#define CP_WAIT(n)  asm volatile("cp.async.wait_group %0;" :: "n"(n) : "memory")

// ============================================================
// split fp32 -> 3 bf16 limbs (optional scale)
// ============================================================
__global__ void __launch_bounds__(256) split3_kernel(
    const float* __restrict__ in, __nv_bfloat16* __restrict__ o0,
    __nv_bfloat16* __restrict__ o1, __nv_bfloat16* __restrict__ o2,
    size_t n4, float scale)
{
    const size_t stride = (size_t)gridDim.x * 256;
    for (size_t i = (size_t)blockIdx.x * 256 + threadIdx.x; i < n4; i += stride) {
        float4 v = ((const float4*)in)[i];
        v.x *= scale; v.y *= scale; v.z *= scale; v.w *= scale;
        float f[4] = {v.x, v.y, v.z, v.w};
        uint16_t l0[4], l1[4], l2[4];
        #pragma unroll
        for (int k = 0; k < 4; k++) {
            __nv_bfloat16 h0 = __float2bfloat16(f[k]);
            float r = f[k] - __bfloat162float(h0);
            __nv_bfloat16 h1 = __float2bfloat16(r);
            float r2 = r - __bfloat162float(h1);
            __nv_bfloat16 h2 = __float2bfloat16(r2);
            l0[k] = *(uint16_t*)&h0; l1[k] = *(uint16_t*)&h1; l2[k] = *(uint16_t*)&h2;
        }
        ((uint2*)o0)[i] = make_uint2(l0[0] | ((uint32_t)l0[1] << 16), l0[2] | ((uint32_t)l0[3] << 16));
        ((uint2*)o1)[i] = make_uint2(l1[0] | ((uint32_t)l1[1] << 16), l1[2] | ((uint32_t)l1[3] << 16));
        ((uint2*)o2)[i] = make_uint2(l2[0] | ((uint32_t)l2[1] << 16), l2[2] | ((uint32_t)l2[3] << 16));
    }
}

// mo fp32 -> bf16 hi/lo (2 limbs, for GEMM2)
__global__ void __launch_bounds__(256) split_kernel(const float* __restrict__ in)
{
    const size_t n4 = (size_t)B_ * DO * THW / 4;
    const size_t stride = (size_t)gridDim.x * 256;
    for (size_t i = (size_t)blockIdx.x * 256 + threadIdx.x; i < n4; i += stride) {
        float4 v = ((const float4*)in)[i];
        __nv_bfloat16 h0 = __float2bfloat16(v.x), h1 = __float2bfloat16(v.y);
        __nv_bfloat16 h2 = __float2bfloat16(v.z), h3 = __float2bfloat16(v.w);
        __nv_bfloat162* H = (__nv_bfloat162*)g_mohi;
        __nv_bfloat162* L = (__nv_bfloat162*)g_molo;
        H[2*i]   = __halves2bfloat162(h0, h1);
        H[2*i+1] = __halves2bfloat162(h2, h3);
        L[2*i]   = __halves2bfloat162(__float2bfloat16(v.x - __bfloat162float(h0)),
                                      __float2bfloat16(v.y - __bfloat162float(h1)));
        L[2*i+1] = __halves2bfloat162(__float2bfloat16(v.z - __bfloat162float(h2)),
                                      __float2bfloat16(v.w - __bfloat162float(h3)));
    }
}

// ============================================================
// WMMA bf16 GEMM1 (3-limb, 6 passes): p = (mi)^T (qi*SCALE)
// 256 threads / 8 warps (4x2), warp tile 32(t) x 64(q), 2 CTAs/SM
// ============================================================
#define TP 136
#define G1_TILE (32 * TP)
#define G1_STAGE (6 * G1_TILE)
#define G1_SMEM (2 * G1_STAGE * 2)              // 104448 bytes

__global__ void __launch_bounds__(256, 2) gemm1_wmma(float* __restrict__ p)
{
    extern __shared__ __nv_bfloat16 dsm[];
    const int b = blockIdx.z;
    const int q0 = blockIdx.x * 128, t0 = blockIdx.y * 128;
    const int tid = threadIdx.x, wid = tid >> 5;
    const int wm = wid & 3, wn = wid >> 2;       // warp tile 32(t) x 64(q)

    const __nv_bfloat16* A0 = g_mi0 + (size_t)b * DE * THW;
    const __nv_bfloat16* A1 = g_mi1 + (size_t)b * DE * THW;
    const __nv_bfloat16* A2 = g_mi2 + (size_t)b * DE * THW;
    const __nv_bfloat16* B0 = g_qi0 + (size_t)b * DE * HW;
    const __nv_bfloat16* B1 = g_qi1 + (size_t)b * DE * HW;
    const __nv_bfloat16* B2 = g_qi2 + (size_t)b * DE * HW;

    const uint32_t sbase = (uint32_t)__cvta_generic_to_shared(dsm);

    auto load_stage = [&](int slot, int k0) {
        uint32_t sb = sbase + (uint32_t)slot * (G1_STAGE * 2);
        #pragma unroll
        for (int l = 0; l < 12; l++) {
            int idx = tid + l * 256;             // 0..3071
            int arr = idx >> 9, rem = idx & 511;
            int row = rem >> 4, col = rem & 15;  // row<32 (d), col*8 elems
            const __nv_bfloat16* src;
            if (arr < 3) {
                src = (arr == 0 ? A0 : arr == 1 ? A1 : A2)
                      + (size_t)(k0 + row) * THW + t0 + col * 8;
            } else {
                src = (arr == 3 ? B0 : arr == 4 ? B1 : B2)
                      + (size_t)(k0 + row) * HW + q0 + col * 8;
            }
            cp16(sb + (uint32_t)arr * (G1_TILE * 2) + row * (TP * 2) + col * 16, src);
        }
    };

    wmma::fragment<wmma::accumulator, 16, 16, 16, float> fc[2][4];
    #pragma unroll
    for (int i = 0; i < 2; i++)
        #pragma unroll
        for (int j = 0; j < 4; j++) wmma::fill_fragment(fc[i][j], 0.f);

    const int NC = DE / 32;   // 4
    load_stage(0, 0);
    CP_COMMIT();

    for (int c = 0; c < NC; c++) {
        if (c + 1 < NC) { load_stage((c + 1) & 1, (c + 1) * 32); CP_COMMIT(); }
        if (c + 1 < NC) CP_WAIT(1); else CP_WAIT(0);
        __syncthreads();

        __nv_bfloat16* st = dsm + (size_t)(c & 1) * G1_STAGE;
        #pragma unroll
        for (int kk = 0; kk < 32; kk += 16) {
            wmma::fragment<wmma::matrix_a, 16, 16, 16, __nv_bfloat16, wmma::col_major> fa[3][2];
            #pragma unroll
            for (int l = 0; l < 3; l++)
                #pragma unroll
                for (int i = 0; i < 2; i++)
                    wmma::load_matrix_sync(fa[l][i],
                        st + l * G1_TILE + kk * TP + wm * 32 + i * 16, TP);
            // B limb 0: x A0, A1, A2
            {
                wmma::fragment<wmma::matrix_b, 16, 16, 16, __nv_bfloat16, wmma::row_major> fb[4];
                #pragma unroll
                for (int j = 0; j < 4; j++)
                    wmma::load_matrix_sync(fb[j],
                        st + 3 * G1_TILE + kk * TP + wn * 64 + j * 16, TP);
                #pragma unroll
                for (int i = 0; i < 2; i++)
                    #pragma unroll
                    for (int j = 0; j < 4; j++) {
                        wmma::mma_sync(fc[i][j], fa[0][i], fb[j], fc[i][j]);
                        wmma::mma_sync(fc[i][j], fa[1][i], fb[j], fc[i][j]);
                        wmma::mma_sync(fc[i][j], fa[2][i], fb[j], fc[i][j]);
                    }
            }
            // B limb 1: x A0, A1
            {
                wmma::fragment<wmma::matrix_b, 16, 16, 16, __nv_bfloat16, wmma::row_major> fb[4];
                #pragma unroll
                for (int j = 0; j < 4; j++)
                    wmma::load_matrix_sync(fb[j],
                        st + 4 * G1_TILE + kk * TP + wn * 64 + j * 16, TP);
                #pragma unroll
                for (int i = 0; i < 2; i++)
                    #pragma unroll
                    for (int j = 0; j < 4; j++) {
                        wmma::mma_sync(fc[i][j], fa[0][i], fb[j], fc[i][j]);
                        wmma::mma_sync(fc[i][j], fa[1][i], fb[j], fc[i][j]);
                    }
            }
            // B limb 2: x A0
            {
                wmma::fragment<wmma::matrix_b, 16, 16, 16, __nv_bfloat16, wmma::row_major> fb[4];
                #pragma unroll
                for (int j = 0; j < 4; j++)
                    wmma::load_matrix_sync(fb[j],
                        st + 5 * G1_TILE + kk * TP + wn * 64 + j * 16, TP);
                #pragma unroll
                for (int i = 0; i < 2; i++)
                    #pragma unroll
                    for (int j = 0; j < 4; j++)
                        wmma::mma_sync(fc[i][j], fa[0][i], fb[j], fc[i][j]);
            }
        }
        __syncthreads();
    }

    // epilogue via smem: 128x128 fp32 tile
    float* sc = (float*)dsm;
    #pragma unroll
    for (int i = 0; i < 2; i++)
        #pragma unroll
        for (int j = 0; j < 4; j++)
            wmma::store_matrix_sync(sc + (size_t)(wm * 32 + i * 16) * 128 + wn * 64 + j * 16,
                                    fc[i][j], 128, wmma::mem_row_major);
    __syncthreads();

    // coalesced p store
    float* C = p + ((size_t)b * THW + t0) * HW + q0;
    #pragma unroll
    for (int l = 0; l < 16; l++) {
        int i = tid + l * 256;                   // 0..4095 float4
        int row = i >> 5, col = (i & 31) << 2;
        *(float4*)(C + (size_t)row * HW + col) = *(float4*)(sc + row * 128 + col);
    }

    // fused argmax partial: 2 threads per row (64 q each)
    {
        int row = tid >> 1, h = tid & 1;
        const float* r = sc + row * 128 + h * 64;
        float bv = r[0];
        int bj = 0;
        #pragma unroll 8
        for (int k = 1; k < 64; k++)
            if (r[k] > bv) { bv = r[k]; bj = k; }
        int gq = q0 + h * 64 + bj;
        float ov = __shfl_xor_sync(~0u, bv, 1);
        int   oi = __shfl_xor_sync(~0u, gq, 1);
        if (ov > bv || (ov == bv && oi < gq)) { bv = ov; gq = oi; }
        if (h == 0)
            g_amax[((size_t)b * THW + t0 + row) * 8 + blockIdx.x] =
                make_float2(bv, (float)gq);
    }
}

// reduce 8 tile-partials per row -> gaussian center
__global__ void __launch_bounds__(256) argmax_final()
{
    int r = blockIdx.x * 256 + threadIdx.x;
    if (r >= B_ * THW) return;
    const float2* a = g_amax + (size_t)r * 8;
    float bv = a[0].x;
    int bi = (int)a[0].y;
    #pragma unroll
    for (int k = 1; k < 8; k++) {
        float2 v = a[k];
        if (v.x > bv) { bv = v.x; bi = (int)v.y; }
    }
    g_center[r] = make_float2((float)(bi & 31), (float)(bi >> 5));
}

// ============================================================
// exp + transpose: e^T bf16 hi/lo + partial sums (p preserved)
// ============================================================
__global__ void __launch_bounds__(256) exp_t_kernel(const float* __restrict__ p)
{
    __shared__ float tile[128][33];
    __shared__ float ssum[8][32];
    const int b = blockIdx.z, t0 = blockIdx.y * 128, q0 = blockIdx.x * 32;
    const int tid = threadIdx.x, tx = tid & 31, ty = tid >> 5;
    const float qx = (float)((q0 + tx) & 31), qy = (float)((q0 + tx) >> 5);
    const float* pc = p + ((size_t)b * THW + t0) * HW + q0 + tx;
    const float2* cen = g_center + (size_t)b * THW + t0;
    float s = 0.f;
    #pragma unroll 4
    for (int r = 0; r < 16; r++) {
        int t = ty * 16 + r;
        float2 c = cen[t];
        float dx = qx - c.x, dy = qy - c.y;
        float v = __expf(pc[(size_t)t * HW] - (dx * dx + dy * dy) * INV2SIG2);
        tile[t][tx] = v;
        s += v;
    }
    ssum[ty][tx] = s;
    __syncthreads();
    if (ty == 0) {
        float a = 0.f;
        #pragma unroll
        for (int k = 0; k < 8; k++) a += ssum[k][tx];
        g_part[((size_t)b * NCHUNK + blockIdx.y) * HW + q0 + tx] = a;
    }
    const int qq = tid & 31, seg = tid >> 5;
    uint32_t hi[8], lo[8];
    #pragma unroll
    for (int k = 0; k < 8; k++) {
        float v0 = tile[seg * 16 + 2 * k][qq], v1 = tile[seg * 16 + 2 * k + 1][qq];
        __nv_bfloat16 h0 = __float2bfloat16(v0), h1 = __float2bfloat16(v1);
        hi[k] = ((uint32_t)*(uint16_t*)&h1 << 16) | *(uint16_t*)&h0;
        __nv_bfloat16 l0 = __float2bfloat16(v0 - __bfloat162float(h0));
        __nv_bfloat16 l1 = __float2bfloat16(v1 - __bfloat162float(h1));
        lo[k] = ((uint32_t)*(uint16_t*)&l1 << 16) | *(uint16_t*)&l0;
    }
    size_t o = ((size_t)b * HW + q0 + qq) * THW + t0 + seg * 16;
    *(uint4*)(g_ehi + o)     = make_uint4(hi[0], hi[1], hi[2], hi[3]);
    *(uint4*)(g_ehi + o + 8) = make_uint4(hi[4], hi[5], hi[6], hi[7]);
    *(uint4*)(g_elo + o)     = make_uint4(lo[0], lo[1], lo[2], lo[3]);
    *(uint4*)(g_elo + o + 8) = make_uint4(lo[4], lo[5], lo[6], lo[7]);
}

__global__ void __launch_bounds__(256) inv_kernel()
{
    int i = blockIdx.x * 256 + threadIdx.x;
    int b = i >> 10, q = i & 1023;
    float s = 0.f;
    #pragma unroll
    for (int c = 0; c < NCHUNK; c++) s += g_part[((size_t)b * NCHUNK + c) * HW + q];
    g_inv[i] = 1.0f / s;
}

// ============================================================
// WMMA bf16 GEMM2, 2-stage cp.async, split-K=2 -> 256 CTAs
// ============================================================
#define KP 40
#define NSTAGE 2
#define TILE_ELEMS (128 * KP)
#define STAGE_ELEMS (4 * TILE_ELEMS)
#define SMEM_DYN (NSTAGE * STAGE_ELEMS * 2)     // 81920 bytes

__global__ void __launch_bounds__(256, 2) gemm2_wmma()
{
    extern __shared__ __nv_bfloat16 dsm[];
    const int b = blockIdx.z >> 1, half = blockIdx.z & 1;
    const int kbase = half * (THW / 2);
    const int q0 = blockIdx.x * 128, o0 = blockIdx.y * 128;
    const int tid = threadIdx.x, wid = tid >> 5;
    const int wm = wid & 3, wn = wid >> 2;

    const __nv_bfloat16* Ah = g_mohi + ((size_t)b * DO + o0) * THW + kbase;
    const __nv_bfloat16* Al = g_molo + ((size_t)b * DO + o0) * THW + kbase;
    const __nv_bfloat16* Bh = g_ehi  + ((size_t)b * HW + q0) * THW + kbase;
    const __nv_bfloat16* Bl = g_elo  + ((size_t)b * HW + q0) * THW + kbase;

    const uint32_t sbase = (uint32_t)__cvta_generic_to_shared(dsm);

    auto load_stage = [&](int slot, int kc) {
        uint32_t sb = sbase + (uint32_t)slot * (STAGE_ELEMS * 2);
        #pragma unroll
        for (int l = 0; l < 8; l++) {
            int idx = tid + l * 256;
            int arr = idx >> 9, rem = idx & 511;
            int row = rem >> 2, ch = rem & 3;
            const __nv_bfloat16* src =
                (arr == 0 ? Ah : arr == 1 ? Al : arr == 2 ? Bh : Bl);
            cp16(sb + (uint32_t)arr * (TILE_ELEMS * 2) + row * (KP * 2) + ch * 16,
                 src + (size_t)row * THW + kc + ch * 8);
        }
    };

    wmma::fragment<wmma::accumulator, 16, 16, 16, float> fc[2][4];
    #pragma unroll
    for (int i = 0; i < 2; i++)
        #pragma unroll
        for (int j = 0; j < 4; j++) wmma::fill_fragment(fc[i][j], 0.f);

    const int NC = (THW / 2) / 32;   // 160

    load_stage(0, 0);
    CP_COMMIT();

    for (int c = 0; c < NC; c++) {
        CP_WAIT(0);
        __syncthreads();
        if (c + 1 < NC) { load_stage((c + 1) & 1, (c + 1) * 32); CP_COMMIT(); }

        __nv_bfloat16* st  = dsm + (size_t)(c & 1) * STAGE_ELEMS;
        __nv_bfloat16* tAh = st;
        __nv_bfloat16* tAl = st + TILE_ELEMS;
        __nv_bfloat16* tBh = st + 2 * TILE_ELEMS;
        __nv_bfloat16* tBl = st + 3 * TILE_ELEMS;

        #pragma unroll
        for (int kk = 0; kk < 32; kk += 16) {
            wmma::fragment<wmma::matrix_a, 16, 16, 16, __nv_bfloat16, wmma::row_major> fah[2], fal[2];
            #pragma unroll
            for (int i = 0; i < 2; i++) {
                wmma::load_matrix_sync(fah[i], tAh + (wm * 32 + i * 16) * KP + kk, KP);
                wmma::load_matrix_sync(fal[i], tAl + (wm * 32 + i * 16) * KP + kk, KP);
            }
            #pragma unroll
            for (int j = 0; j < 4; j++) {
                wmma::fragment<wmma::matrix_b, 16, 16, 16, __nv_bfloat16, wmma::col_major> fbh, fbl;
                wmma::load_matrix_sync(fbh, tBh + (wn * 64 + j * 16) * KP + kk, KP);
                wmma::load_matrix_sync(fbl, tBl + (wn * 64 + j * 16) * KP + kk, KP);
                #pragma unroll
                for (int i = 0; i < 2; i++) {
                    wmma::mma_sync(fc[i][j], fah[i], fbh, fc[i][j]);
                    wmma::mma_sync(fc[i][j], fah[i], fbl, fc[i][j]);
                    wmma::mma_sync(fc[i][j], fal[i], fbh, fc[i][j]);
                }
            }
        }
        __syncthreads();
    }

    float* C = g_cpart + (((size_t)half * B_ + b) * DO + o0) * HW + q0;
    #pragma unroll
    for (int i = 0; i < 2; i++)
        #pragma unroll
        for (int j = 0; j < 4; j++)
            wmma::store_matrix_sync(C + (size_t)(wm * 32 + i * 16) * HW + wn * 64 + j * 16,
                                    fc[i][j], HW, wmma::mem_row_major);
}

// combine split-K halves + apply inv -> out[:, :Do]
__global__ void __launch_bounds__(256) combine_kernel(float* __restrict__ out)
{
    const size_t n4 = (size_t)B_ * DO * HW / 4;
    size_t i = (size_t)blockIdx.x * 256 + threadIdx.x;
    if (i >= n4) return;
    float4 a = ((const float4*)g_cpart)[i];
    float4 c = ((const float4*)g_cpart)[i + n4];
    size_t q4 = i & 255;
    size_t b  = i / ((size_t)DO * HW / 4);
    float4 inv = ((const float4*)g_inv)[b * 256 + q4];
    float4 v = make_float4((a.x + c.x) * inv.x, (a.y + c.y) * inv.y,
                           (a.z + c.z) * inv.z, (a.w + c.w) * inv.w);
    size_t r = i - b * ((size_t)DO * HW / 4);
    ((float4*)out)[b * ((size_t)2 * DO * HW / 4) + r] = v;
}

__global__ void __launch_bounds__(256) copy_qout_kernel(
    const float* __restrict__ q_out, float* __restrict__ out)
{
    const size_t per_b4 = (size_t)DO * HW / 4;
    size_t i = (size_t)blockIdx.x * 256 + threadIdx.x;
    if (i >= (size_t)B_ * per_b4) return;
    size_t b = i / per_b4, r = i - b * per_b4;
    ((float4*)out)[b * 2 * per_b4 + per_b4 + r] = ((const float4*)q_out)[i];
}

// p_w fp32 output from ehi/elo (no exp): transpose [b][q][t] -> [b][t][q], *inv
__global__ void __launch_bounds__(256) pw_t_kernel(float* __restrict__ dst)
{
    __shared__ float tile[32][129];
    __shared__ float sinv[32];
    const int b = blockIdx.z, t0 = blockIdx.y * 128, q0 = blockIdx.x * 32;
    const int tid = threadIdx.x;

    {
        int q = tid >> 3, seg = tid & 7;
        size_t o = ((size_t)b * HW + q0 + q) * THW + t0 + seg * 16;
        uint4 h0 = *(const uint4*)(g_ehi + o);
        uint4 h1 = *(const uint4*)(g_ehi + o + 8);
        uint4 l0 = *(const uint4*)(g_elo + o);
        uint4 l1 = *(const uint4*)(g_elo + o + 8);
        const uint32_t hw_[8] = {h0.x, h0.y, h0.z, h0.w, h1.x, h1.y, h1.z, h1.w};
        const uint32_t lw_[8] = {l0.x, l0.y, l0.z, l0.w, l1.x, l1.y, l1.z, l1.w};
        #pragma unroll
        for (int k = 0; k < 8; k++) {
            __nv_bfloat162 hv = *(const __nv_bfloat162*)&hw_[k];
            __nv_bfloat162 lv = *(const __nv_bfloat162*)&lw_[k];
            tile[q][seg * 16 + 2 * k]     = __bfloat162float(hv.x) + __bfloat162float(lv.x);
            tile[q][seg * 16 + 2 * k + 1] = __bfloat162float(hv.y) + __bfloat162float(lv.y);
        }
    }
    if (tid < 32) sinv[tid] = g_inv[(size_t)b * HW + q0 + tid];
    __syncthreads();

    int t = tid >> 1, qs = (tid & 1) * 16;
    float* d = dst + ((size_t)b * THW + t0 + t) * HW + q0 + qs;
    #pragma unroll
    for (int k = 0; k < 16; k += 4) {
        float4 v = make_float4(tile[qs + k][t]     * sinv[qs + k],
                               tile[qs + k + 1][t] * sinv[qs + k + 1],
                               tile[qs + k + 2][t] * sinv[qs + k + 2],
                               tile[qs + k + 3][t] * sinv[qs + k + 3]);
        *(float4*)(d + k) = v;
    }
}

// ============================================================
extern "C" void kernel_launch(void* const* d_in, const int* in_sizes, int n_in,
                              void* d_out, int out_size)
{
    const float* m_in  = (const float*)d_in[0];
    const float* m_out = (const float*)d_in[1];
    const float* q_in  = (const float*)d_in[2];
    const float* q_out = (const float*)d_in[3];
    float* out = (float*)d_out;

    float* p = nullptr;
    cudaGetSymbolAddress((void**)&p, g_p);
    __nv_bfloat16 *mi0, *mi1, *mi2, *qi0, *qi1, *qi2;
    cudaGetSymbolAddress((void**)&mi0, g_mi0);
    cudaGetSymbolAddress((void**)&mi1, g_mi1);
    cudaGetSymbolAddress((void**)&mi2, g_mi2);
    cudaGetSymbolAddress((void**)&qi0, g_qi0);
    cudaGetSymbolAddress((void**)&qi1, g_qi1);
    cudaGetSymbolAddress((void**)&qi2, g_qi2);

    cudaFuncSetAttribute(gemm1_wmma, cudaFuncAttributeMaxDynamicSharedMemorySize, G1_SMEM);
    cudaFuncSetAttribute(gemm2_wmma, cudaFuncAttributeMaxDynamicSharedMemorySize, SMEM_DYN);

    // 0) split mi (3 limbs), qi*SCALE (3 limbs), mo (2 limbs)
    split3_kernel<<<2048, 256>>>(m_in, mi0, mi1, mi2, (size_t)B_ * DE * THW / 4, 1.0f);
    split3_kernel<<<512, 256>>>(q_in, qi0, qi1, qi2, (size_t)B_ * DE * HW / 4, SCALE);
    split_kernel<<<4096, 256>>>(m_out);

    // 1) p = mi^T (qi*SCALE) via WMMA 3-limb + fused argmax partials
    dim3 g1(HW / 128, THW / 128, B_);   // (8, 80, 4)
    gemm1_wmma<<<g1, 256, G1_SMEM>>>(p);

    // 2) argmax final reduce -> centers
    argmax_final<<<(B_ * THW + 255) / 256, 256>>>();

    // 3) exp + transpose + partial sums
    dim3 g3(HW / 32, THW / 128, B_);
    exp_t_kernel<<<g3, 256>>>(p);

    // 4) inv
    inv_kernel<<<(B_ * HW) / 256, 256>>>();

    // 5) WMMA bf16 GEMM2, split-K=2 -> 256 CTAs
    dim3 g4(HW / 128, DO / 128, B_ * 2);
    gemm2_wmma<<<g4, 256, SMEM_DYN>>>();

    // 6) combine halves + normalize -> out[:, :Do]
    combine_kernel<<<(B_ * DO * HW / 4 + 255) / 256, 256>>>(out);

    // 7) out[:, Do:] = q_out
    copy_qout_kernel<<<(B_ * DO * HW / 4 + 255) / 256, 256>>>(q_out, out);

    // 8) optional p_w output (from ehi/elo, no exp)
    const size_t memout = (size_t)B_ * 2 * DO * HW;
    const size_t pw     = (size_t)B_ * THW * HW;
    if ((size_t)out_size >= memout + pw) {
        dim3 g5(HW / 32, THW / 128, B_);
        pw_t_kernel<<<g5, 256>>>(out + memout);
    }
}

// round 11
// speedup vs baseline: 1.1728x; 1.0493x over previous
#include <cuda_runtime.h>
#include <cuda_bf16.h>
#include <mma.h>
#include <cstdint>
#include <math.h>

using namespace nvcuda;

#define B_    4
#define DE    128
#define DO    512
#define THW   10240
#define HW    1024
#define NCHUNK 80
#define SCALE 0.08838834764831845f
#define INV2SIG2 (1.0f/18.0f)

// ---------------- device scratch ----------------
__device__ float         g_p[(size_t)B_ * THW * HW];       // p fp32 (preserved)
__device__ __nv_bfloat16 g_ehi[(size_t)B_ * HW * THW];     // e^T [b][q][t] hi
__device__ __nv_bfloat16 g_elo[(size_t)B_ * HW * THW];
__device__ __nv_bfloat16 g_mohi[(size_t)B_ * DO * THW];
__device__ __nv_bfloat16 g_molo[(size_t)B_ * DO * THW];
__device__ __nv_bfloat16 g_mi0[(size_t)B_ * DE * THW];     // mi 3 limbs [b][d][t]
__device__ __nv_bfloat16 g_mi1[(size_t)B_ * DE * THW];
__device__ __nv_bfloat16 g_mi2[(size_t)B_ * DE * THW];
__device__ __nv_bfloat16 g_qi0[(size_t)B_ * DE * HW];      // qi*SCALE 3 limbs [b][d][q]
__device__ __nv_bfloat16 g_qi1[(size_t)B_ * DE * HW];
__device__ __nv_bfloat16 g_qi2[(size_t)B_ * DE * HW];
__device__ float         g_cpart[(size_t)2 * B_ * DO * HW]; // split-K partials
__device__ float2        g_center[B_ * THW];
__device__ float2        g_amax[(size_t)B_ * THW * 8];     // per-qtile argmax partials
__device__ float         g_part[(size_t)B_ * NCHUNK * HW];
__device__ float         g_inv[B_ * HW];

__device__ __forceinline__ void cp16(uint32_t sa, const void* g) {
    asm volatile("cp.async.cg.shared.global [%0], [%1], 16;" :: "r"(sa), "l"(g));
}
#define CP_COMMIT() asm volatile("cp.async.commit_group;" ::: "memory")
#define CP_WAIT(n)  asm volatile("cp.async.wait_group %0;" :: "n"(n) : "memory")

// ============================================================
// split fp32 -> 3 bf16 limbs (optional scale)
// ============================================================
__global__ void __launch_bounds__(256) split3_kernel(
    const float* __restrict__ in, __nv_bfloat16* __restrict__ o0,
    __nv_bfloat16* __restrict__ o1, __nv_bfloat16* __restrict__ o2,
    size_t n4, float scale)
{
    const size_t stride = (size_t)gridDim.x * 256;
    for (size_t i = (size_t)blockIdx.x * 256 + threadIdx.x; i < n4; i += stride) {
        float4 v = ((const float4*)in)[i];
        v.x *= scale; v.y *= scale; v.z *= scale; v.w *= scale;
        float f[4] = {v.x, v.y, v.z, v.w};
        uint16_t l0[4], l1[4], l2[4];
        #pragma unroll
        for (int k = 0; k < 4; k++) {
            __nv_bfloat16 h0 = __float2bfloat16(f[k]);
            float r = f[k] - __bfloat162float(h0);
            __nv_bfloat16 h1 = __float2bfloat16(r);
            float r2 = r - __bfloat162float(h1);
            __nv_bfloat16 h2 = __float2bfloat16(r2);
            l0[k] = *(uint16_t*)&h0; l1[k] = *(uint16_t*)&h1; l2[k] = *(uint16_t*)&h2;
        }
        ((uint2*)o0)[i] = make_uint2(l0[0] | ((uint32_t)l0[1] << 16), l0[2] | ((uint32_t)l0[3] << 16));
        ((uint2*)o1)[i] = make_uint2(l1[0] | ((uint32_t)l1[1] << 16), l1[2] | ((uint32_t)l1[3] << 16));
        ((uint2*)o2)[i] = make_uint2(l2[0] | ((uint32_t)l2[1] << 16), l2[2] | ((uint32_t)l2[3] << 16));
    }
}

// mo fp32 -> bf16 hi/lo (2 limbs, for GEMM2)
__global__ void __launch_bounds__(256) split_kernel(const float* __restrict__ in)
{
    const size_t n4 = (size_t)B_ * DO * THW / 4;
    const size_t stride = (size_t)gridDim.x * 256;
    for (size_t i = (size_t)blockIdx.x * 256 + threadIdx.x; i < n4; i += stride) {
        float4 v = ((const float4*)in)[i];
        __nv_bfloat16 h0 = __float2bfloat16(v.x), h1 = __float2bfloat16(v.y);
        __nv_bfloat16 h2 = __float2bfloat16(v.z), h3 = __float2bfloat16(v.w);
        __nv_bfloat162* H = (__nv_bfloat162*)g_mohi;
        __nv_bfloat162* L = (__nv_bfloat162*)g_molo;
        H[2*i]   = __halves2bfloat162(h0, h1);
        H[2*i+1] = __halves2bfloat162(h2, h3);
        L[2*i]   = __halves2bfloat162(__float2bfloat16(v.x - __bfloat162float(h0)),
                                      __float2bfloat16(v.y - __bfloat162float(h1)));
        L[2*i+1] = __halves2bfloat162(__float2bfloat16(v.z - __bfloat162float(h2)),
                                      __float2bfloat16(v.w - __bfloat162float(h3)));
    }
}

// ============================================================
// WMMA bf16 GEMM1 (3-limb, 6 passes): p = (mi)^T (qi*SCALE)
// 256 threads / 8 warps (4x2), warp tile 32(t) x 64(q), 2 CTAs/SM
// ============================================================
#define TP 136
#define G1_TILE (32 * TP)
#define G1_STAGE (6 * G1_TILE)
#define G1_SMEM (2 * G1_STAGE * 2)              // 104448 bytes

__global__ void __launch_bounds__(256, 2) gemm1_wmma(float* __restrict__ p)
{
    extern __shared__ __nv_bfloat16 dsm[];
    const int b = blockIdx.z;
    const int q0 = blockIdx.x * 128, t0 = blockIdx.y * 128;
    const int tid = threadIdx.x, wid = tid >> 5;
    const int wm = wid & 3, wn = wid >> 2;       // warp tile 32(t) x 64(q)

    const __nv_bfloat16* A0 = g_mi0 + (size_t)b * DE * THW;
    const __nv_bfloat16* A1 = g_mi1 + (size_t)b * DE * THW;
    const __nv_bfloat16* A2 = g_mi2 + (size_t)b * DE * THW;
    const __nv_bfloat16* B0 = g_qi0 + (size_t)b * DE * HW;
    const __nv_bfloat16* B1 = g_qi1 + (size_t)b * DE * HW;
    const __nv_bfloat16* B2 = g_qi2 + (size_t)b * DE * HW;

    const uint32_t sbase = (uint32_t)__cvta_generic_to_shared(dsm);

    auto load_stage = [&](int slot, int k0) {
        uint32_t sb = sbase + (uint32_t)slot * (G1_STAGE * 2);
        #pragma unroll
        for (int l = 0; l < 12; l++) {
            int idx = tid + l * 256;             // 0..3071
            int arr = idx >> 9, rem = idx & 511;
            int row = rem >> 4, col = rem & 15;  // row<32 (d), col*8 elems
            const __nv_bfloat16* src;
            if (arr < 3) {
                src = (arr == 0 ? A0 : arr == 1 ? A1 : A2)
                      + (size_t)(k0 + row) * THW + t0 + col * 8;
            } else {
                src = (arr == 3 ? B0 : arr == 4 ? B1 : B2)
                      + (size_t)(k0 + row) * HW + q0 + col * 8;
            }
            cp16(sb + (uint32_t)arr * (G1_TILE * 2) + row * (TP * 2) + col * 16, src);
        }
    };

    wmma::fragment<wmma::accumulator, 16, 16, 16, float> fc[2][4];
    #pragma unroll
    for (int i = 0; i < 2; i++)
        #pragma unroll
        for (int j = 0; j < 4; j++) wmma::fill_fragment(fc[i][j], 0.f);

    const int NC = DE / 32;   // 4
    load_stage(0, 0);
    CP_COMMIT();

    for (int c = 0; c < NC; c++) {
        if (c + 1 < NC) { load_stage((c + 1) & 1, (c + 1) * 32); CP_COMMIT(); }
        if (c + 1 < NC) CP_WAIT(1); else CP_WAIT(0);
        __syncthreads();

        __nv_bfloat16* st = dsm + (size_t)(c & 1) * G1_STAGE;
        #pragma unroll
        for (int kk = 0; kk < 32; kk += 16) {
            wmma::fragment<wmma::matrix_a, 16, 16, 16, __nv_bfloat16, wmma::col_major> fa[3][2];
            #pragma unroll
            for (int l = 0; l < 3; l++)
                #pragma unroll
                for (int i = 0; i < 2; i++)
                    wmma::load_matrix_sync(fa[l][i],
                        st + l * G1_TILE + kk * TP + wm * 32 + i * 16, TP);
            // B limb 0: x A0, A1, A2
            {
                wmma::fragment<wmma::matrix_b, 16, 16, 16, __nv_bfloat16, wmma::row_major> fb[4];
                #pragma unroll
                for (int j = 0; j < 4; j++)
                    wmma::load_matrix_sync(fb[j],
                        st + 3 * G1_TILE + kk * TP + wn * 64 + j * 16, TP);
                #pragma unroll
                for (int i = 0; i < 2; i++)
                    #pragma unroll
                    for (int j = 0; j < 4; j++) {
                        wmma::mma_sync(fc[i][j], fa[0][i], fb[j], fc[i][j]);
                        wmma::mma_sync(fc[i][j], fa[1][i], fb[j], fc[i][j]);
                        wmma::mma_sync(fc[i][j], fa[2][i], fb[j], fc[i][j]);
                    }
            }
            // B limb 1: x A0, A1
            {
                wmma::fragment<wmma::matrix_b, 16, 16, 16, __nv_bfloat16, wmma::row_major> fb[4];
                #pragma unroll
                for (int j = 0; j < 4; j++)
                    wmma::load_matrix_sync(fb[j],
                        st + 4 * G1_TILE + kk * TP + wn * 64 + j * 16, TP);
                #pragma unroll
                for (int i = 0; i < 2; i++)
                    #pragma unroll
                    for (int j = 0; j < 4; j++) {
                        wmma::mma_sync(fc[i][j], fa[0][i], fb[j], fc[i][j]);
                        wmma::mma_sync(fc[i][j], fa[1][i], fb[j], fc[i][j]);
                    }
            }
            // B limb 2: x A0
            {
                wmma::fragment<wmma::matrix_b, 16, 16, 16, __nv_bfloat16, wmma::row_major> fb[4];
                #pragma unroll
                for (int j = 0; j < 4; j++)
                    wmma::load_matrix_sync(fb[j],
                        st + 5 * G1_TILE + kk * TP + wn * 64 + j * 16, TP);
                #pragma unroll
                for (int i = 0; i < 2; i++)
                    #pragma unroll
                    for (int j = 0; j < 4; j++)
                        wmma::mma_sync(fc[i][j], fa[0][i], fb[j], fc[i][j]);
            }
        }
        __syncthreads();
    }

    // epilogue via smem: 128x128 fp32 tile
    float* sc = (float*)dsm;
    #pragma unroll
    for (int i = 0; i < 2; i++)
        #pragma unroll
        for (int j = 0; j < 4; j++)
            wmma::store_matrix_sync(sc + (size_t)(wm * 32 + i * 16) * 128 + wn * 64 + j * 16,
                                    fc[i][j], 128, wmma::mem_row_major);
    __syncthreads();

    // coalesced p store
    float* C = p + ((size_t)b * THW + t0) * HW + q0;
    #pragma unroll
    for (int l = 0; l < 16; l++) {
        int i = tid + l * 256;                   // 0..4095 float4
        int row = i >> 5, col = (i & 31) << 2;
        *(float4*)(C + (size_t)row * HW + col) = *(float4*)(sc + row * 128 + col);
    }

    // fused argmax partial: 2 threads per row (64 q each)
    {
        int row = tid >> 1, h = tid & 1;
        const float* r = sc + row * 128 + h * 64;
        float bv = r[0];
        int bj = 0;
        #pragma unroll 8
        for (int k = 1; k < 64; k++)
            if (r[k] > bv) { bv = r[k]; bj = k; }
        int gq = q0 + h * 64 + bj;
        float ov = __shfl_xor_sync(~0u, bv, 1);
        int   oi = __shfl_xor_sync(~0u, gq, 1);
        if (ov > bv || (ov == bv && oi < gq)) { bv = ov; gq = oi; }
        if (h == 0)
            g_amax[((size_t)b * THW + t0 + row) * 8 + blockIdx.x] =
                make_float2(bv, (float)gq);
    }
}

// reduce 8 tile-partials per row -> gaussian center
__global__ void __launch_bounds__(256) argmax_final()
{
    int r = blockIdx.x * 256 + threadIdx.x;
    if (r >= B_ * THW) return;
    const float2* a = g_amax + (size_t)r * 8;
    float bv = a[0].x;
    int bi = (int)a[0].y;
    #pragma unroll
    for (int k = 1; k < 8; k++) {
        float2 v = a[k];
        if (v.x > bv) { bv = v.x; bi = (int)v.y; }
    }
    g_center[r] = make_float2((float)(bi & 31), (float)(bi >> 5));
}

// ============================================================
// exp + transpose: e^T bf16 hi/lo + partial sums (p preserved)
// smem tile transposed [q][t] -> conflict-free exp writes +
// fully coalesced (256B/8-lane) global bf16 writes
// ============================================================
__global__ void __launch_bounds__(256) exp_t_kernel(const float* __restrict__ p)
{
    __shared__ float tile[32][129];    // [q][t], stride 129 = conflict-free col writes
    __shared__ float ssum[8][32];
    const int b = blockIdx.z, t0 = blockIdx.y * 128, q0 = blockIdx.x * 32;
    const int tid = threadIdx.x, tx = tid & 31, ty = tid >> 5;
    const float qx = (float)((q0 + tx) & 31), qy = (float)((q0 + tx) >> 5);
    const float* pc = p + ((size_t)b * THW + t0) * HW + q0 + tx;
    const float2* cen = g_center + (size_t)b * THW + t0;
    float s = 0.f;
    #pragma unroll 4
    for (int r = 0; r < 16; r++) {
        int t = ty * 16 + r;
        float2 c = cen[t];
        float dx = qx - c.x, dy = qy - c.y;
        float v = __expf(pc[(size_t)t * HW] - (dx * dx + dy * dy) * INV2SIG2);
        tile[tx][t] = v;
        s += v;
    }
    ssum[ty][tx] = s;
    __syncthreads();
    if (ty == 0) {
        float a = 0.f;
        #pragma unroll
        for (int k = 0; k < 8; k++) a += ssum[k][tx];
        g_part[((size_t)b * NCHUNK + blockIdx.y) * HW + q0 + tx] = a;
    }
    // bf16 hi/lo write: thread handles q-row qq, 16 contiguous t
    const int qq = tid >> 3, seg = tid & 7;
    uint32_t hi[8], lo[8];
    #pragma unroll
    for (int k = 0; k < 8; k++) {
        float v0 = tile[qq][seg * 16 + 2 * k];
        float v1 = tile[qq][seg * 16 + 2 * k + 1];
        __nv_bfloat16 h0 = __float2bfloat16(v0), h1 = __float2bfloat16(v1);
        hi[k] = ((uint32_t)*(uint16_t*)&h1 << 16) | *(uint16_t*)&h0;
        __nv_bfloat16 l0 = __float2bfloat16(v0 - __bfloat162float(h0));
        __nv_bfloat16 l1 = __float2bfloat16(v1 - __bfloat162float(h1));
        lo[k] = ((uint32_t)*(uint16_t*)&l1 << 16) | *(uint16_t*)&l0;
    }
    size_t o = ((size_t)b * HW + q0 + qq) * THW + t0 + seg * 16;
    *(uint4*)(g_ehi + o)     = make_uint4(hi[0], hi[1], hi[2], hi[3]);
    *(uint4*)(g_ehi + o + 8) = make_uint4(hi[4], hi[5], hi[6], hi[7]);
    *(uint4*)(g_elo + o)     = make_uint4(lo[0], lo[1], lo[2], lo[3]);
    *(uint4*)(g_elo + o + 8) = make_uint4(lo[4], lo[5], lo[6], lo[7]);
}

__global__ void __launch_bounds__(256) inv_kernel()
{
    int i = blockIdx.x * 256 + threadIdx.x;
    int b = i >> 10, q = i & 1023;
    float s = 0.f;
    #pragma unroll
    for (int c = 0; c < NCHUNK; c++) s += g_part[((size_t)b * NCHUNK + c) * HW + q];
    g_inv[i] = 1.0f / s;
}

// ============================================================
// WMMA bf16 GEMM2 v3 (CUTLASS-style ILP config):
// CTA 128(o) x 256(q), 8 warps, warp tile 64x64 (16 acc frags),
// K-chunk 32, 3-stage cp.async, split-K=2 -> 128 CTAs (1 wave)
// ============================================================
#define KP 40
#define A_ROWS 128
#define B_ROWS 256
#define A_TILE_E (A_ROWS * KP)                  // 5120 elems / limb
#define B_TILE_E (B_ROWS * KP)                  // 10240
#define STAGE_E (2 * A_TILE_E + 2 * B_TILE_E)   // 30720 elems
#define SMEM_DYN (3 * STAGE_E * 2)              // 184320 bytes

__global__ void __launch_bounds__(256) gemm2_wmma()
{
    extern __shared__ __nv_bfloat16 dsm[];
    const int b = blockIdx.z >> 1, half = blockIdx.z & 1;
    const int kbase = half * (THW / 2);
    const int q0 = blockIdx.x * 256, o0 = blockIdx.y * 128;
    const int tid = threadIdx.x, wid = tid >> 5;
    const int wm = wid & 1, wn = wid >> 1;       // 2(o) x 4(q) warps, tile 64x64

    const __nv_bfloat16* Ah = g_mohi + ((size_t)b * DO + o0) * THW + kbase;
    const __nv_bfloat16* Al = g_molo + ((size_t)b * DO + o0) * THW + kbase;
    const __nv_bfloat16* Bh = g_ehi  + ((size_t)b * HW + q0) * THW + kbase;
    const __nv_bfloat16* Bl = g_elo  + ((size_t)b * HW + q0) * THW + kbase;

    const uint32_t sbase = (uint32_t)__cvta_generic_to_shared(dsm);

    auto load_stage = [&](int slot, int kc) {
        uint32_t sb = sbase + (uint32_t)slot * (STAGE_E * 2);
        #pragma unroll
        for (int l = 0; l < 12; l++) {
            int idx = tid + l * 256;             // 0..3071
            if (idx < 1024) {                    // A: 2 limbs x 128 rows x 4 cp16
                int limb = idx >> 9, r = (idx >> 2) & 127, ch = idx & 3;
                const __nv_bfloat16* src = (limb ? Al : Ah) + (size_t)r * THW + kc + ch * 8;
                cp16(sb + (uint32_t)limb * (A_TILE_E * 2) + r * (KP * 2) + ch * 16, src);
            } else {                             // B: 2 limbs x 256 rows x 4 cp16
                int idx2 = idx - 1024;
                int limb = idx2 >> 10, r = (idx2 >> 2) & 255, ch = idx2 & 3;
                const __nv_bfloat16* src = (limb ? Bl : Bh) + (size_t)r * THW + kc + ch * 8;
                cp16(sb + (uint32_t)(2 * A_TILE_E + limb * B_TILE_E) * 2
                        + r * (KP * 2) + ch * 16, src);
            }
        }
    };

    wmma::fragment<wmma::accumulator, 16, 16, 16, float> fc[4][4];
    #pragma unroll
    for (int i = 0; i < 4; i++)
        #pragma unroll
        for (int j = 0; j < 4; j++) wmma::fill_fragment(fc[i][j], 0.f);

    const int NC = (THW / 2) / 32;   // 160

    load_stage(0, 0);  CP_COMMIT();
    load_stage(1, 32); CP_COMMIT();

    for (int c = 0; c < NC; c++) {
        CP_WAIT(1);
        __syncthreads();
        if (c + 2 < NC) { load_stage((c + 2) % 3, (c + 2) * 32); CP_COMMIT(); }

        __nv_bfloat16* st  = dsm + (size_t)(c % 3) * STAGE_E;
        __nv_bfloat16* tAh = st;
        __nv_bfloat16* tAl = st + A_TILE_E;
        __nv_bfloat16* tBh = st + 2 * A_TILE_E;
        __nv_bfloat16* tBl = tBh + B_TILE_E;

        #pragma unroll
        for (int kk = 0; kk < 32; kk += 16) {
            wmma::fragment<wmma::matrix_a, 16, 16, 16, __nv_bfloat16, wmma::row_major> fah[4], fal[4];
            #pragma unroll
            for (int i = 0; i < 4; i++) {
                wmma::load_matrix_sync(fah[i], tAh + (wm * 64 + i * 16) * KP + kk, KP);
                wmma::load_matrix_sync(fal[i], tAl + (wm * 64 + i * 16) * KP + kk, KP);
            }
            #pragma unroll
            for (int j = 0; j < 4; j++) {
                wmma::fragment<wmma::matrix_b, 16, 16, 16, __nv_bfloat16, wmma::col_major> fbh, fbl;
                wmma::load_matrix_sync(fbh, tBh + (wn * 64 + j * 16) * KP + kk, KP);
                wmma::load_matrix_sync(fbl, tBl + (wn * 64 + j * 16) * KP + kk, KP);
                #pragma unroll
                for (int i = 0; i < 4; i++) {
                    wmma::mma_sync(fc[i][j], fah[i], fbh, fc[i][j]);
                    wmma::mma_sync(fc[i][j], fah[i], fbl, fc[i][j]);
                    wmma::mma_sync(fc[i][j], fal[i], fbh, fc[i][j]);
                }
            }
        }
    }
    CP_WAIT(0);

    float* C = g_cpart + (((size_t)half * B_ + b) * DO + o0 + wm * 64) * HW + q0 + wn * 64;
    #pragma unroll
    for (int i = 0; i < 4; i++)
        #pragma unroll
        for (int j = 0; j < 4; j++)
            wmma::store_matrix_sync(C + (size_t)(i * 16) * HW + j * 16,
                                    fc[i][j], HW, wmma::mem_row_major);
}

// combine split-K halves + apply inv -> out[:, :Do]
__global__ void __launch_bounds__(256) combine_kernel(float* __restrict__ out)
{
    const size_t n4 = (size_t)B_ * DO * HW / 4;
    size_t i = (size_t)blockIdx.x * 256 + threadIdx.x;
    if (i >= n4) return;
    float4 a = ((const float4*)g_cpart)[i];
    float4 c = ((const float4*)g_cpart)[i + n4];
    size_t q4 = i & 255;
    size_t b  = i / ((size_t)DO * HW / 4);
    float4 inv = ((const float4*)g_inv)[b * 256 + q4];
    float4 v = make_float4((a.x + c.x) * inv.x, (a.y + c.y) * inv.y,
                           (a.z + c.z) * inv.z, (a.w + c.w) * inv.w);
    size_t r = i - b * ((size_t)DO * HW / 4);
    ((float4*)out)[b * ((size_t)2 * DO * HW / 4) + r] = v;
}

__global__ void __launch_bounds__(256) copy_qout_kernel(
    const float* __restrict__ q_out, float* __restrict__ out)
{
    const size_t per_b4 = (size_t)DO * HW / 4;
    size_t i = (size_t)blockIdx.x * 256 + threadIdx.x;
    if (i >= (size_t)B_ * per_b4) return;
    size_t b = i / per_b4, r = i - b * per_b4;
    ((float4*)out)[b * 2 * per_b4 + per_b4 + r] = ((const float4*)q_out)[i];
}

// p_w fp32 output from ehi/elo (no exp): transpose [b][q][t] -> [b][t][q], *inv
__global__ void __launch_bounds__(256) pw_t_kernel(float* __restrict__ dst)
{
    __shared__ float tile[32][129];
    __shared__ float sinv[32];
    const int b = blockIdx.z, t0 = blockIdx.y * 128, q0 = blockIdx.x * 32;
    const int tid = threadIdx.x;

    {
        int q = tid >> 3, seg = tid & 7;
        size_t o = ((size_t)b * HW + q0 + q) * THW + t0 + seg * 16;
        uint4 h0 = *(const uint4*)(g_ehi + o);
        uint4 h1 = *(const uint4*)(g_ehi + o + 8);
        uint4 l0 = *(const uint4*)(g_elo + o);
        uint4 l1 = *(const uint4*)(g_elo + o + 8);
        const uint32_t hw_[8] = {h0.x, h0.y, h0.z, h0.w, h1.x, h1.y, h1.z, h1.w};
        const uint32_t lw_[8] = {l0.x, l0.y, l0.z, l0.w, l1.x, l1.y, l1.z, l1.w};
        #pragma unroll
        for (int k = 0; k < 8; k++) {
            __nv_bfloat162 hv = *(const __nv_bfloat162*)&hw_[k];
            __nv_bfloat162 lv = *(const __nv_bfloat162*)&lw_[k];
            tile[q][seg * 16 + 2 * k]     = __bfloat162float(hv.x) + __bfloat162float(lv.x);
            tile[q][seg * 16 + 2 * k + 1] = __bfloat162float(hv.y) + __bfloat162float(lv.y);
        }
    }
    if (tid < 32) sinv[tid] = g_inv[(size_t)b * HW + q0 + tid];
    __syncthreads();

    int t = tid >> 1, qs = (tid & 1) * 16;
    float* d = dst + ((size_t)b * THW + t0 + t) * HW + q0 + qs;
    #pragma unroll
    for (int k = 0; k < 16; k += 4) {
        float4 v = make_float4(tile[qs + k][t]     * sinv[qs + k],
                               tile[qs + k + 1][t] * sinv[qs + k + 1],
                               tile[qs + k + 2][t] * sinv[qs + k + 2],
                               tile[qs + k + 3][t] * sinv[qs + k + 3]);
        *(float4*)(d + k) = v;
    }
}

// ============================================================
extern "C" void kernel_launch(void* const* d_in, const int* in_sizes, int n_in,
                              void* d_out, int out_size)
{
    const float* m_in  = (const float*)d_in[0];
    const float* m_out = (const float*)d_in[1];
    const float* q_in  = (const float*)d_in[2];
    const float* q_out = (const float*)d_in[3];
    float* out = (float*)d_out;

    float* p = nullptr;
    cudaGetSymbolAddress((void**)&p, g_p);
    __nv_bfloat16 *mi0, *mi1, *mi2, *qi0, *qi1, *qi2;
    cudaGetSymbolAddress((void**)&mi0, g_mi0);
    cudaGetSymbolAddress((void**)&mi1, g_mi1);
    cudaGetSymbolAddress((void**)&mi2, g_mi2);
    cudaGetSymbolAddress((void**)&qi0, g_qi0);
    cudaGetSymbolAddress((void**)&qi1, g_qi1);
    cudaGetSymbolAddress((void**)&qi2, g_qi2);

    cudaFuncSetAttribute(gemm1_wmma, cudaFuncAttributeMaxDynamicSharedMemorySize, G1_SMEM);
    cudaFuncSetAttribute(gemm2_wmma, cudaFuncAttributeMaxDynamicSharedMemorySize, SMEM_DYN);

    // 0) split mi (3 limbs), qi*SCALE (3 limbs), mo (2 limbs)
    split3_kernel<<<2048, 256>>>(m_in, mi0, mi1, mi2, (size_t)B_ * DE * THW / 4, 1.0f);
    split3_kernel<<<512, 256>>>(q_in, qi0, qi1, qi2, (size_t)B_ * DE * HW / 4, SCALE);
    split_kernel<<<4096, 256>>>(m_out);

    // 1) p = mi^T (qi*SCALE) via WMMA 3-limb + fused argmax partials
    dim3 g1(HW / 128, THW / 128, B_);   // (8, 80, 4)
    gemm1_wmma<<<g1, 256, G1_SMEM>>>(p);

    // 2) argmax final reduce -> centers
    argmax_final<<<(B_ * THW + 255) / 256, 256>>>();

    // 3) exp + transpose + partial sums
    dim3 g3(HW / 32, THW / 128, B_);
    exp_t_kernel<<<g3, 256>>>(p);

    // 4) inv
    inv_kernel<<<(B_ * HW) / 256, 256>>>();

    // 5) WMMA bf16 GEMM2 v3: 128x256 CTA, 64x64 warp tile, 3-stage
    dim3 g4(HW / 256, DO / 128, B_ * 2);   // (4, 4, 8) = 128 CTAs
    gemm2_wmma<<<g4, 256, SMEM_DYN>>>();

    // 6) combine halves + normalize -> out[:, :Do]
    combine_kernel<<<(B_ * DO * HW / 4 + 255) / 256, 256>>>(out);

    // 7) out[:, Do:] = q_out
    copy_qout_kernel<<<(B_ * DO * HW / 4 + 255) / 256, 256>>>(q_out, out);

    // 8) optional p_w output (from ehi/elo, no exp)
    const size_t memout = (size_t)B_ * 2 * DO * HW;
    const size_t pw     = (size_t)B_ * THW * HW;
    if ((size_t)out_size >= memout + pw) {
        dim3 g5(HW / 32, THW / 128, B_);
        pw_t_kernel<<<g5, 256>>>(out + memout);
    }
}